// round 7
// baseline (speedup 1.0000x reference)
#include <cuda_runtime.h>
#include <cuda_bf16.h>
#include <math.h>
#include <stdint.h>

// Problem constants
#define BB   2
#define LS   2048
#define DM   1024
#define DIN  2048
#define DST  16
#define RDT  64
#define ML   (BB*LS)      // 4096 rows
#define DFF  (4*DM)       // 4096

typedef __nv_bfloat16 bf16;

// ---------------- scratch (device globals) -----------------------------------
// xz unified: [ML][8192], cols [dir*4096 .. +2047]=xi, [+2048..+4095]=z
__device__ __align__(256) float  g_xz  [(size_t)ML * 8192];
__device__ __align__(256) float  g_xc  [2u * ML * DIN];
__device__ __align__(256) float  g_xdbl[2u * ML * 96];     // cols 64..95: B/C interleaved
__device__ __align__(256) float4 g_dtuz[(size_t)2 * BB * DIN * LS];  // [dir][b][d][l] (dt,u,z,_)
__device__ __align__(256) float  g_ydir[2u * ML * DM];
__device__ __align__(256) float  g_xsum[(size_t)ML * DM];

__device__ __align__(256) bf16 g_xhi [(size_t)ML * DM],  g_xlo [(size_t)ML * DM];
__device__ __align__(256) bf16 g_yhi [2u * ML * DIN],    g_ylo [2u * ML * DIN];
__device__ __align__(256) bf16 g_lnhi[(size_t)ML * DM],  g_lnlo[(size_t)ML * DM];
__device__ __align__(256) bf16 g_f1hi[(size_t)ML * DFF], g_f1lo[(size_t)ML * DFF];
__device__ __align__(256) bf16 g_inwhi [2u * 2 * DIN * DM], g_inwlo [2u * 2 * DIN * DM];
__device__ __align__(256) bf16 g_outwhi[2u * DM * DIN],     g_outwlo[2u * DM * DIN];
__device__ __align__(256) bf16 g_w1hi[(size_t)DFF * DM],  g_w1lo[(size_t)DFF * DM];
__device__ __align__(256) bf16 g_w2hi[(size_t)DM * DFF],  g_w2lo[(size_t)DM * DFF];

// ---------------- helpers ------------------------------------------------------
__device__ __forceinline__ float siluf(float v) { return v / (1.f + __expf(-v)); }
__device__ __forceinline__ float softplusf(float v) {
    return (v > 20.f) ? v : log1pf(__expf(v));
}
__device__ __forceinline__ void split1(float f, unsigned short& h, unsigned short& l) {
    __nv_bfloat16 hb = __float2bfloat16(f);
    h = __bfloat16_as_ushort(hb);
    l = __bfloat16_as_ushort(__float2bfloat16(f - __bfloat162float(hb)));
}

#define LDSM4(r0, r1, r2, r3, addr) \
    asm volatile("ldmatrix.sync.aligned.m8n8.x4.shared.b16 {%0,%1,%2,%3}, [%4];" \
        : "=r"(r0), "=r"(r1), "=r"(r2), "=r"(r3) : "r"(addr))

#define MMA16816(d, a, b0, b1) \
    asm volatile("mma.sync.aligned.m16n8k16.row.col.f32.bf16.bf16.f32 " \
        "{%0,%1,%2,%3}, {%4,%5,%6,%7}, {%8,%9}, {%0,%1,%2,%3};" \
        : "+f"((d)[0]), "+f"((d)[1]), "+f"((d)[2]), "+f"((d)[3]) \
        : "r"((a)[0]), "r"((a)[1]), "r"((a)[2]), "r"((a)[3]), "r"(b0), "r"(b1))

#define CPA16(sa, ga) \
    asm volatile("cp.async.cg.shared.global [%0], [%1], 16;" :: "r"(sa), "l"(ga))
#define CPA_COMMIT() asm volatile("cp.async.commit_group;" ::: "memory")
#define CPA_WAIT1()  asm volatile("cp.async.wait_group 1;" ::: "memory")

// ---------------- split-bf16 tensor-core GEMM (pre-split inputs) ---------------
#define KC       32
#define ARR_B    8192
#define STAGE_B  (4 * ARR_B)
#define NSTAGE   3
#define DSMEM2   (NSTAGE * STAGE_B)

__global__ __launch_bounds__(256, 2)
void mma_gemm2(const bf16* __restrict__ Ahi, const bf16* __restrict__ Alo, int lda,
               const bf16* __restrict__ Bhi, const bf16* __restrict__ Blo, int ldb,
               const float* __restrict__ bias,
               const float* __restrict__ addsrc,
               float* __restrict__ Cf,
               bf16* __restrict__ Chi, bf16* __restrict__ Clo,
               int ldc, int K, int act,
               size_t zsA, size_t zsB, size_t zsC)
{
    extern __shared__ char sm[];
    const int tid  = threadIdx.x;
    const int lane = tid & 31;
    const int wid  = tid >> 5;
    const int wm   = wid >> 2;
    const int wn   = wid & 3;
    const int rowBase = blockIdx.y * 128;
    const int colBase = blockIdx.x * 128;
    const size_t zA = (size_t)blockIdx.z * zsA;
    const size_t zB = (size_t)blockIdx.z * zsB;
    const size_t zC = (size_t)blockIdx.z * zsC;
    const uint32_t smb = (uint32_t)__cvta_generic_to_shared(sm);

    const int crow = tid >> 2;
    const int cck  = tid & 3;
    const size_t offA0 = zA + (size_t)(rowBase + crow) * lda + cck * 8;
    const size_t offA1 = zA + (size_t)(rowBase + crow + 64) * lda + cck * 8;
    const size_t offB0 = zB + (size_t)(colBase + crow) * ldb + cck * 8;
    const size_t offB1 = zB + (size_t)(colBase + crow + 64) * ldb + cck * 8;
    const uint32_t s0 = (uint32_t)crow * 64        + (uint32_t)((cck ^ ((crow >> 1) & 3)) * 16);
    const uint32_t s1 = (uint32_t)(crow + 64) * 64 + (uint32_t)((cck ^ (((crow + 64) >> 1) & 3)) * 16);

    const int laneAr = (lane & 7) + ((lane >> 3) & 1) * 8;
    const int aCk    = (lane >> 4);
    const int laneBr = (lane & 7) + ((lane >> 4) & 1) * 8;
    const int bCk    = (lane >> 3) & 1;
    uint32_t aRowB[4], aSw[4], bRowB[2], bSw[2];
    #pragma unroll
    for (int i = 0; i < 4; i++) {
        int r = wm * 64 + i * 16 + laneAr;
        aRowB[i] = (uint32_t)r * 64;
        aSw[i]   = (uint32_t)((r >> 1) & 3);
    }
    #pragma unroll
    for (int p = 0; p < 2; p++) {
        int r = wn * 32 + p * 16 + laneBr;
        bRowB[p] = (uint32_t)r * 64;
        bSw[p]   = (uint32_t)((r >> 1) & 3);
    }

    float acc[16][4];
    #pragma unroll
    for (int i = 0; i < 16; i++)
        #pragma unroll
        for (int j = 0; j < 4; j++) acc[i][j] = 0.f;

    const int nk = K / KC;

    auto issue = [&](int stg, int kt) {
        const uint32_t sb = smb + (uint32_t)stg * STAGE_B;
        const size_t ko = (size_t)kt * KC;
        CPA16(sb + 0*ARR_B + s0, Ahi + offA0 + ko);
        CPA16(sb + 0*ARR_B + s1, Ahi + offA1 + ko);
        CPA16(sb + 1*ARR_B + s0, Alo + offA0 + ko);
        CPA16(sb + 1*ARR_B + s1, Alo + offA1 + ko);
        CPA16(sb + 2*ARR_B + s0, Bhi + offB0 + ko);
        CPA16(sb + 2*ARR_B + s1, Bhi + offB1 + ko);
        CPA16(sb + 3*ARR_B + s0, Blo + offB0 + ko);
        CPA16(sb + 3*ARR_B + s1, Blo + offB1 + ko);
    };

    issue(0, 0); CPA_COMMIT();
    issue(1, 1); CPA_COMMIT();

    int stg = 0;
    for (int kt = 0; kt < nk; kt++) {
        CPA_WAIT1();
        __syncthreads();
        if (kt + 2 < nk) issue((stg + 2) % NSTAGE, kt + 2);
        CPA_COMMIT();

        const uint32_t base = smb + (uint32_t)stg * STAGE_B;
        #pragma unroll
        for (int ks = 0; ks < 2; ks++) {
            uint32_t aH[4][4], aL[4][4], bH[2][4], bL[2][4];
            #pragma unroll
            for (int i = 0; i < 4; i++)
                LDSM4(aH[i][0], aH[i][1], aH[i][2], aH[i][3],
                      base + 0*ARR_B + aRowB[i] + (((uint32_t)(ks*2 + aCk) ^ aSw[i]) * 16));
            #pragma unroll
            for (int p = 0; p < 2; p++)
                LDSM4(bH[p][0], bH[p][1], bH[p][2], bH[p][3],
                      base + 2*ARR_B + bRowB[p] + (((uint32_t)(ks*2 + bCk) ^ bSw[p]) * 16));
            #pragma unroll
            for (int i = 0; i < 4; i++)
                #pragma unroll
                for (int nt = 0; nt < 4; nt++)
                    MMA16816(acc[i*4+nt], aH[i], bH[nt>>1][(nt&1)*2], bH[nt>>1][(nt&1)*2+1]);
            #pragma unroll
            for (int i = 0; i < 4; i++)
                LDSM4(aL[i][0], aL[i][1], aL[i][2], aL[i][3],
                      base + 1*ARR_B + aRowB[i] + (((uint32_t)(ks*2 + aCk) ^ aSw[i]) * 16));
            #pragma unroll
            for (int i = 0; i < 4; i++)
                #pragma unroll
                for (int nt = 0; nt < 4; nt++)
                    MMA16816(acc[i*4+nt], aL[i], bH[nt>>1][(nt&1)*2], bH[nt>>1][(nt&1)*2+1]);
            #pragma unroll
            for (int p = 0; p < 2; p++)
                LDSM4(bL[p][0], bL[p][1], bL[p][2], bL[p][3],
                      base + 3*ARR_B + bRowB[p] + (((uint32_t)(ks*2 + bCk) ^ bSw[p]) * 16));
            #pragma unroll
            for (int i = 0; i < 4; i++)
                #pragma unroll
                for (int nt = 0; nt < 4; nt++)
                    MMA16816(acc[i*4+nt], aH[i], bL[nt>>1][(nt&1)*2], bL[nt>>1][(nt&1)*2+1]);
        }
        stg = (stg + 1) % NSTAGE;
    }

    const int erow  = wm * 64 + (lane >> 2);
    const int ecol0 = wn * 32 + (lane & 3) * 2;
    #pragma unroll
    for (int i = 0; i < 4; i++) {
        int r0 = rowBase + erow + i * 16;
        int r1 = r0 + 8;
        #pragma unroll
        for (int nt = 0; nt < 4; nt++) {
            int c = colBase + ecol0 + nt * 8;
            float v0 = acc[i*4+nt][0], v1 = acc[i*4+nt][1];
            float v2 = acc[i*4+nt][2], v3 = acc[i*4+nt][3];
            if (bias) {
                float b0 = __ldg(&bias[c]), b1 = __ldg(&bias[c+1]);
                v0 += b0; v1 += b1; v2 += b0; v3 += b1;
            }
            if (act == 1) { v0 = siluf(v0); v1 = siluf(v1); v2 = siluf(v2); v3 = siluf(v3); }
            else if (act == 2) { v0 = softplusf(v0); v1 = softplusf(v1); v2 = softplusf(v2); v3 = softplusf(v3); }
            if (addsrc) {
                v0 += addsrc[(size_t)r0 * ldc + c];
                v1 += addsrc[(size_t)r0 * ldc + c + 1];
                v2 += addsrc[(size_t)r1 * ldc + c];
                v3 += addsrc[(size_t)r1 * ldc + c + 1];
            }
            if (Cf) {
                *(float2*)&Cf[zC + (size_t)r0 * ldc + c] = make_float2(v0, v1);
                *(float2*)&Cf[zC + (size_t)r1 * ldc + c] = make_float2(v2, v3);
            } else {
                unsigned short h0,h1,h2,h3,l0,l1,l2,l3;
                split1(v0, h0, l0); split1(v1, h1, l1);
                split1(v2, h2, l2); split1(v3, h3, l3);
                *(uint32_t*)(Chi + zC + (size_t)r0 * ldc + c) = (uint32_t)h0 | ((uint32_t)h1 << 16);
                *(uint32_t*)(Clo + zC + (size_t)r0 * ldc + c) = (uint32_t)l0 | ((uint32_t)l1 << 16);
                *(uint32_t*)(Chi + zC + (size_t)r1 * ldc + c) = (uint32_t)h2 | ((uint32_t)h3 << 16);
                *(uint32_t*)(Clo + zC + (size_t)r1 * ldc + c) = (uint32_t)l2 | ((uint32_t)l3 << 16);
            }
        }
    }
}

// ---------------- fp32 -> bf16 hi/lo split --------------------------------------
__global__ void split_kernel(const float* __restrict__ in,
                             bf16* __restrict__ hi,
                             bf16* __restrict__ lo, int n4)
{
    int i = blockIdx.x * blockDim.x + threadIdx.x;
    if (i >= n4) return;
    float4 v = ((const float4*)in)[i];
    unsigned short h0,h1,h2,h3,l0,l1,l2,l3;
    split1(v.x, h0, l0); split1(v.y, h1, l1);
    split1(v.z, h2, l2); split1(v.w, h3, l3);
    uint2 hu, lu;
    hu.x = (uint32_t)h0 | ((uint32_t)h1 << 16);
    hu.y = (uint32_t)h2 | ((uint32_t)h3 << 16);
    lu.x = (uint32_t)l0 | ((uint32_t)l1 << 16);
    lu.y = (uint32_t)l2 | ((uint32_t)l3 << 16);
    *(uint2*)(hi + (size_t)i * 4) = hu;
    *(uint2*)(lo + (size_t)i * 4) = lu;
}

// ---------------- xdbl GEMM: [2][ML][96], B/C interleaved in cols 64..95 --------
__global__ __launch_bounds__(128)
void xdbl_gemm(const float* __restrict__ xcA,
               const float* __restrict__ xw0,
               const float* __restrict__ xw1,
               float* __restrict__ out)
{
    __shared__ float As[16][36];
    __shared__ float Bs[16][100];
    const int dir = blockIdx.z;
    const float* A = xcA + (size_t)dir * ML * DIN + (size_t)blockIdx.x * 32 * DIN;
    const float* B = dir ? xw1 : xw0;
    float* C = out + (size_t)dir * ML * 96 + (size_t)blockIdx.x * 32 * 96;

    const int tid = threadIdx.x;
    const int tx = tid & 15, ty = tid >> 4;
    float acc[4][6];
    #pragma unroll
    for (int i = 0; i < 4; i++)
        #pragma unroll
        for (int j = 0; j < 6; j++) acc[i][j] = 0.f;

    const int ar = tid >> 2, akc = (tid & 3) * 4;

    for (int k0 = 0; k0 < DIN; k0 += 16) {
        {
            float4 v = *(const float4*)(A + (size_t)ar * DIN + k0 + akc);
            As[akc+0][ar] = v.x; As[akc+1][ar] = v.y;
            As[akc+2][ar] = v.z; As[akc+3][ar] = v.w;
        }
        #pragma unroll
        for (int j = 0; j < 3; j++) {
            int i = tid + j * 128;
            int n = i >> 2, kc = (i & 3) * 4;
            float4 v = *(const float4*)(B + (size_t)n * DIN + k0 + kc);
            Bs[kc+0][n] = v.x; Bs[kc+1][n] = v.y;
            Bs[kc+2][n] = v.z; Bs[kc+3][n] = v.w;
        }
        __syncthreads();
        #pragma unroll
        for (int kk = 0; kk < 16; kk++) {
            float4 a4 = *(const float4*)&As[kk][ty*4];
            float ar4[4] = {a4.x, a4.y, a4.z, a4.w};
            float2 b0 = *(const float2*)&Bs[kk][tx*6];
            float2 b1 = *(const float2*)&Bs[kk][tx*6+2];
            float2 b2 = *(const float2*)&Bs[kk][tx*6+4];
            float br[6] = {b0.x, b0.y, b1.x, b1.y, b2.x, b2.y};
            #pragma unroll
            for (int i = 0; i < 4; i++)
                #pragma unroll
                for (int j = 0; j < 6; j++)
                    acc[i][j] = fmaf(ar4[i], br[j], acc[i][j]);
        }
        __syncthreads();
    }
    #pragma unroll
    for (int i = 0; i < 4; i++)
        #pragma unroll
        for (int j = 0; j < 6; j++) {
            int c = tx*6 + j;
            int cw = (c < 64) ? c : ((c < 80) ? (64 + 2*(c - 64)) : (65 + 2*(c - 80)));
            C[(size_t)(ty*4+i) * 96 + cw] = acc[i][j];
        }
}

// ---------------- dt GEMM -> transposed (dt,u,z,_) float4 stream ----------------
__global__ __launch_bounds__(256)
void dt_gemm(const float* __restrict__ xdblA,
             const float* __restrict__ xcA,
             const float* __restrict__ xz,
             const float* __restrict__ w0, const float* __restrict__ w1,
             const float* __restrict__ b0, const float* __restrict__ b1,
             float4* __restrict__ dtuz)       // [dir][b][d][l]
{
    __shared__ float As[16][132];
    __shared__ float Bs[16][132];

    const int dir = blockIdx.z;
    const float* A = xdblA + (size_t)dir * ML * 96;
    const float* xcD = xcA + (size_t)dir * ML * DIN;
    const float* Bw = dir ? w1 : w0;
    const float* bias = dir ? b1 : b0;

    const int tid = threadIdx.x;
    const int tx = tid & 15;
    const int ty = tid >> 4;
    const int rowBase = blockIdx.y * 128;
    const int colBase = blockIdx.x * 128;

    const int lm = tid >> 1;
    const int lk = (tid & 1) * 8;

    const float* aPtr = A + (size_t)(rowBase + lm) * 96 + lk;
    const float* bPtr = Bw + (size_t)(colBase + lm) * RDT + lk;

    float acc[8][8];
    #pragma unroll
    for (int i = 0; i < 8; i++)
        #pragma unroll
        for (int j = 0; j < 8; j++) acc[i][j] = 0.f;

    for (int k0 = 0; k0 < RDT; k0 += 16) {
        float4 a0 = *(const float4*)(aPtr + k0);
        float4 a1 = *(const float4*)(aPtr + k0 + 4);
        float4 b0v = *(const float4*)(bPtr + k0);
        float4 b1v = *(const float4*)(bPtr + k0 + 4);

        As[lk+0][lm] = a0.x; As[lk+1][lm] = a0.y; As[lk+2][lm] = a0.z; As[lk+3][lm] = a0.w;
        As[lk+4][lm] = a1.x; As[lk+5][lm] = a1.y; As[lk+6][lm] = a1.z; As[lk+7][lm] = a1.w;
        Bs[lk+0][lm] = b0v.x; Bs[lk+1][lm] = b0v.y; Bs[lk+2][lm] = b0v.z; Bs[lk+3][lm] = b0v.w;
        Bs[lk+4][lm] = b1v.x; Bs[lk+5][lm] = b1v.y; Bs[lk+6][lm] = b1v.z; Bs[lk+7][lm] = b1v.w;
        __syncthreads();

        #pragma unroll
        for (int kk = 0; kk < 16; kk++) {
            float4 ra0 = *(const float4*)&As[kk][ty * 4];
            float4 ra1 = *(const float4*)&As[kk][64 + ty * 4];
            float4 rb0 = *(const float4*)&Bs[kk][tx * 4];
            float4 rb1 = *(const float4*)&Bs[kk][64 + tx * 4];
            float ar[8] = {ra0.x, ra0.y, ra0.z, ra0.w, ra1.x, ra1.y, ra1.z, ra1.w};
            float br[8] = {rb0.x, rb0.y, rb0.z, rb0.w, rb1.x, rb1.y, rb1.z, rb1.w};
            #pragma unroll
            for (int i = 0; i < 8; i++)
                #pragma unroll
                for (int j = 0; j < 8; j++)
                    acc[i][j] = fmaf(ar[i], br[j], acc[i][j]);
        }
        __syncthreads();
    }

    #pragma unroll
    for (int i = 0; i < 8; i++) {
        int r = rowBase + ((i < 4) ? (ty * 4 + i) : (64 + ty * 4 + i - 4));
        int bq = r >> 11;
        int l  = r & (LS - 1);
        #pragma unroll
        for (int j = 0; j < 8; j++) {
            int c = colBase + ((j < 4) ? (tx * 4 + j) : (64 + tx * 4 + j - 4));
            float dtv = softplusf(acc[i][j] + bias[c]);
            float uv  = xcD[(size_t)r * DIN + c];
            float zv  = xz[(size_t)r * 8192 + dir * 4096 + 2048 + c];
            size_t idx = (((size_t)(dir * 2 + bq) * DIN) + c) * LS + l;
            dtuz[idx] = make_float4(dtv, uv, zv, 0.f);
        }
    }
}

// ---------------- depthwise causal conv (k=4, dir-dependent taps) ---------------
__global__ void conv_kernel(const float* __restrict__ xz,
                            const float* __restrict__ cw0, const float* __restrict__ cw1,
                            const float* __restrict__ cb0, const float* __restrict__ cb1,
                            float* __restrict__ xc)
{
    int idx = blockIdx.x * blockDim.x + threadIdx.x;
    if (idx >= 2 * ML * DIN) return;
    int dir = idx >= ML * DIN;
    int li = dir ? (idx - ML * DIN) : idx;
    int c = li & (DIN - 1);
    int r = li / DIN;
    int l = r & (LS - 1);
    int b = r >> 11;
    const float* cw = dir ? cw1 : cw0;
    const float* cb = dir ? cb1 : cb0;
    float acc = cb[c];
    float w0 = cw[c*4+0], w1 = cw[c*4+1], w2 = cw[c*4+2], w3 = cw[c*4+3];
    size_t colOff = (size_t)dir * 4096 + c;
    if (!dir) {
        #pragma unroll
        for (int k = 0; k < 4; k++) {
            int lp = l - 3 + k;
            if (lp >= 0) {
                float w = (k==0)?w0:(k==1)?w1:(k==2)?w2:w3;
                acc += xz[(size_t)(b * LS + lp) * 8192 + colOff] * w;
            }
        }
    } else {
        #pragma unroll
        for (int k = 0; k < 4; k++) {
            int lp = l + 3 - k;
            if (lp < LS) {
                float w = (k==0)?w0:(k==1)?w1:(k==2)?w2:w3;
                acc += xz[(size_t)(b * LS + lp) * 8192 + colOff] * w;
            }
        }
    }
    xc[(size_t)dir * ML * DIN + (size_t)r * DIN + c] = siluf(acc);
}

// ---------------- selective scan: block = (dir, b, 16 d); coalesced I/O ---------
__global__ __launch_bounds__(256)
void scan_kernel(const float4* __restrict__ dtuz,   // [dir][b][d][l]
                 const float* __restrict__ xdbl,    // [2][ML][96] (B/C paired)
                 const float* __restrict__ A0, const float* __restrict__ A1,
                 const float* __restrict__ D0, const float* __restrict__ D1,
                 bf16* __restrict__ yhi, bf16* __restrict__ ylo)   // [2][ML][DIN]
{
    __shared__ unsigned short syh[32][16];
    __shared__ unsigned short syl[32][16];

    const int tid  = threadIdx.x;
    const int wid  = tid >> 5;
    const int lane = tid & 31;
    const int half = lane >> 4;
    const int s    = lane & 15;

    const int dg  = blockIdx.x & 127;
    const int b   = (blockIdx.x >> 7) & 1;
    const int dir = blockIdx.x >> 8;
    const int dloc = wid * 2 + half;       // 0..15
    const int d    = dg * 16 + dloc;

    const float* Alog = dir ? A1 : A0;
    const float Av = -__expf(Alog[d * DST + s]);
    const float Dd = (dir ? D1 : D0)[d];
    float h = 0.f;
    const bool w0lane = (s == 0);

    const int l0 = dir ? (LS - 1) : 0;
    const int step = dir ? -1 : 1;

    const float4* pD = dtuz + ((size_t)(dir * 2 + b) * DIN + d) * LS;
    const float* pBC = xdbl + (size_t)dir * ML * 96 + ((size_t)b * LS + l0) * 96 + RDT + 2 * s;
    const ptrdiff_t sBC = (ptrdiff_t)step * 96;
    const size_t yBase = (size_t)dir * ML * DIN + (size_t)b * LS * DIN;

    int l = l0;
    float4 duz = pD[l];
    float2 bc = *(const float2*)pBC;
    const float* pBCc = pBC;

    for (int it = 0; it < LS; it++) {
        const bool more = (it + 1 < LS);
        const int ln = more ? (l + step) : l;
        float4 duzn = pD[ln];
        const float* pBCn = more ? (pBCc + sBC) : pBCc;
        float2 bcn = *(const float2*)pBCn;

        h = h * __expf(duz.x * Av) + duz.x * duz.y * bc.x;
        float y = h * bc.y;
        y += __shfl_xor_sync(0xffffffffu, y, 8);
        y += __shfl_xor_sync(0xffffffffu, y, 4);
        y += __shfl_xor_sync(0xffffffffu, y, 2);
        y += __shfl_xor_sync(0xffffffffu, y, 1);
        if (w0lane) {
            float yv = (y + duz.y * Dd) * siluf(duz.z);
            __nv_bfloat16 hb = __float2bfloat16(yv);
            syh[it & 31][dloc] = __bfloat16_as_ushort(hb);
            syl[it & 31][dloc] =
                __bfloat16_as_ushort(__float2bfloat16(yv - __bfloat162float(hb)));
        }
        if ((it & 31) == 31) {
            __syncthreads();
            const int row = tid >> 3;        // 0..31
            const int cp  = tid & 7;         // 0..7
            const int itr = (it - 31) + row;
            const int gl  = l0 + step * itr;
            const size_t go = yBase + (size_t)gl * DIN + dg * 16 + 2 * cp;
            *(uint32_t*)(yhi + go) = *(const uint32_t*)&syh[row][2 * cp];
            *(uint32_t*)(ylo + go) = *(const uint32_t*)&syl[row][2 * cp];
            __syncthreads();
        }
        l = ln; duz = duzn; bc = bcn; pBCc = pBCn;
    }
}

// ---------------- fused residual + layernorm -> xsum + bf16 hi/lo ----------------
__global__ void resln_kernel(const float* __restrict__ x,
                             const float* __restrict__ y0,
                             const float* __restrict__ y1,
                             const float* __restrict__ g,
                             const float* __restrict__ bta,
                             float* __restrict__ xsum,
                             bf16* __restrict__ outhi,
                             bf16* __restrict__ outlo)
{
    int row = blockIdx.x;
    size_t off4 = (size_t)row * (DM / 4) + threadIdx.x;
    float4 xv = ((const float4*)x)[off4];
    float4 a = ((const float4*)y0)[off4];
    float4 b = ((const float4*)y1)[off4];
    float4 v;
    v.x = xv.x + 0.5f * (a.x + b.x);
    v.y = xv.y + 0.5f * (a.y + b.y);
    v.z = xv.z + 0.5f * (a.z + b.z);
    v.w = xv.w + 0.5f * (a.w + b.w);
    ((float4*)xsum)[off4] = v;

    float s  = v.x + v.y + v.z + v.w;
    float sq = v.x*v.x + v.y*v.y + v.z*v.z + v.w*v.w;
    #pragma unroll
    for (int o = 16; o >= 1; o >>= 1) {
        s  += __shfl_xor_sync(0xffffffffu, s, o);
        sq += __shfl_xor_sync(0xffffffffu, sq, o);
    }
    __shared__ float ss[8], ssq[8];
    int warp = threadIdx.x >> 5, lane = threadIdx.x & 31;
    if (lane == 0) { ss[warp] = s; ssq[warp] = sq; }
    __syncthreads();
    __shared__ float sh_mean, sh_inv;
    if (threadIdx.x == 0) {
        float ts = 0.f, tq = 0.f;
        #pragma unroll
        for (int w = 0; w < 8; w++) { ts += ss[w]; tq += ssq[w]; }
        float mean = ts / DM;
        float var = tq / DM - mean * mean;
        sh_mean = mean;
        sh_inv = rsqrtf(var + 1e-5f);
    }
    __syncthreads();
    float mean = sh_mean, inv = sh_inv;
    float4 gv = ((const float4*)g)[threadIdx.x];
    float4 bv = ((const float4*)bta)[threadIdx.x];
    float o0 = (v.x - mean) * inv * gv.x + bv.x;
    float o1 = (v.y - mean) * inv * gv.y + bv.y;
    float o2 = (v.z - mean) * inv * gv.z + bv.z;
    float o3 = (v.w - mean) * inv * gv.w + bv.w;
    unsigned short h0,h1,h2,h3,l0,l1,l2,l3;
    split1(o0, h0, l0); split1(o1, h1, l1);
    split1(o2, h2, l2); split1(o3, h3, l3);
    uint2 hu, lu;
    hu.x = (uint32_t)h0 | ((uint32_t)h1 << 16);
    hu.y = (uint32_t)h2 | ((uint32_t)h3 << 16);
    lu.x = (uint32_t)l0 | ((uint32_t)l1 << 16);
    lu.y = (uint32_t)l2 | ((uint32_t)l3 << 16);
    size_t off = (size_t)row * DM + threadIdx.x * 4;
    *(uint2*)(outhi + off) = hu;
    *(uint2*)(outlo + off) = lu;
}

// ---------------- host orchestration ----------------------------------------------
extern "C" void kernel_launch(void* const* d_in, const int* in_sizes, int n_in,
                              void* d_out, int out_size)
{
    (void)in_sizes; (void)n_in; (void)out_size;

    const float* x = (const float*)d_in[0];
    const float* in_w[2]   = { (const float*)d_in[1],  (const float*)d_in[10] };
    const float* conv_w[2] = { (const float*)d_in[2],  (const float*)d_in[11] };
    const float* conv_b[2] = { (const float*)d_in[3],  (const float*)d_in[12] };
    const float* x_w[2]    = { (const float*)d_in[4],  (const float*)d_in[13] };
    const float* dt_w[2]   = { (const float*)d_in[5],  (const float*)d_in[14] };
    const float* dt_b[2]   = { (const float*)d_in[6],  (const float*)d_in[15] };
    const float* A_log[2]  = { (const float*)d_in[7],  (const float*)d_in[16] };
    const float* Dp[2]     = { (const float*)d_in[8],  (const float*)d_in[17] };
    const float* out_w[2]  = { (const float*)d_in[9],  (const float*)d_in[18] };
    const float* ff_ln_g = (const float*)d_in[19];
    const float* ff_ln_b = (const float*)d_in[20];
    const float* ff_w1   = (const float*)d_in[21];
    const float* ff_b1   = (const float*)d_in[22];
    const float* ff_w2   = (const float*)d_in[23];
    const float* ff_b2   = (const float*)d_in[24];

    float *xz, *xc, *xdbl, *ydir, *xsum;
    float4 *dtuz;
    bf16 *xhi, *xlo, *yhi, *ylo, *lnhi, *lnlo, *f1hi, *f1lo;
    bf16 *inwhi, *inwlo, *outwhi, *outwlo, *w1hi, *w1lo, *w2hi, *w2lo;
    cudaGetSymbolAddress((void**)&xz,   g_xz);
    cudaGetSymbolAddress((void**)&xc,   g_xc);
    cudaGetSymbolAddress((void**)&xdbl, g_xdbl);
    cudaGetSymbolAddress((void**)&dtuz, g_dtuz);
    cudaGetSymbolAddress((void**)&ydir, g_ydir);
    cudaGetSymbolAddress((void**)&xsum, g_xsum);
    cudaGetSymbolAddress((void**)&xhi,  g_xhi);
    cudaGetSymbolAddress((void**)&xlo,  g_xlo);
    cudaGetSymbolAddress((void**)&yhi,  g_yhi);
    cudaGetSymbolAddress((void**)&ylo,  g_ylo);
    cudaGetSymbolAddress((void**)&lnhi, g_lnhi);
    cudaGetSymbolAddress((void**)&lnlo, g_lnlo);
    cudaGetSymbolAddress((void**)&f1hi, g_f1hi);
    cudaGetSymbolAddress((void**)&f1lo, g_f1lo);
    cudaGetSymbolAddress((void**)&inwhi,  g_inwhi);
    cudaGetSymbolAddress((void**)&inwlo,  g_inwlo);
    cudaGetSymbolAddress((void**)&outwhi, g_outwhi);
    cudaGetSymbolAddress((void**)&outwlo, g_outwlo);
    cudaGetSymbolAddress((void**)&w1hi, g_w1hi);
    cudaGetSymbolAddress((void**)&w1lo, g_w1lo);
    cudaGetSymbolAddress((void**)&w2hi, g_w2hi);
    cudaGetSymbolAddress((void**)&w2lo, g_w2lo);

    cudaFuncSetAttribute(mma_gemm2, cudaFuncAttributeMaxDynamicSharedMemorySize, DSMEM2);

    const size_t szXC   = (size_t)ML * DIN;
    const size_t szYDIR = (size_t)ML * DM;
    const size_t szINW  = (size_t)2 * DIN * DM;
    const size_t szOUTW = (size_t)DM * DIN;

    dim3 blk(256);

    // idx 0-2: splits needed for in-proj
    split_kernel<<<(ML*DM/4 + 255)/256, blk>>>(x, xhi, xlo, ML*DM/4);
    split_kernel<<<((int)szINW/4 + 255)/256, blk>>>(in_w[0], inwhi,         inwlo,         (int)szINW/4);
    split_kernel<<<((int)szINW/4 + 255)/256, blk>>>(in_w[1], inwhi + szINW, inwlo + szINW, (int)szINW/4);

    // idx 3 (profiled): merged in-proj, M=4096, N=8192, K=1024
    mma_gemm2<<<dim3(64, 32, 1), blk, DSMEM2>>>(
        xhi, xlo, DM, inwhi, inwlo, DM,
        nullptr, nullptr, xz, nullptr, nullptr,
        8192, DM, 0, 0, 0, 0);

    // remaining splits
    split_kernel<<<(DFF*DM/4 + 255)/256, blk>>>(ff_w1, w1hi, w1lo, DFF*DM/4);
    split_kernel<<<((int)szOUTW/4 + 255)/256, blk>>>(out_w[0], outwhi,          outwlo,          (int)szOUTW/4);
    split_kernel<<<((int)szOUTW/4 + 255)/256, blk>>>(out_w[1], outwhi + szOUTW, outwlo + szOUTW, (int)szOUTW/4);
    split_kernel<<<(DM*DFF/4 + 255)/256, blk>>>(ff_w2, w2hi, w2lo, DM*DFF/4);

    // conv (both dirs)
    conv_kernel<<<(2*ML*DIN + 255)/256, blk>>>(xz, conv_w[0], conv_w[1],
                                               conv_b[0], conv_b[1], xc);

    // xdbl (both dirs), B/C interleaved
    xdbl_gemm<<<dim3(ML/32, 1, 2), dim3(128)>>>(xc, x_w[0], x_w[1], xdbl);

    // dt (both dirs) -> transposed (dt,u,z) float4
    dt_gemm<<<dim3(DIN/128, ML/128, 2), blk>>>(xdbl, xc, xz, dt_w[0], dt_w[1],
                                               dt_b[0], dt_b[1], dtuz);

    // scan (both dirs): 512 blocks = 2 dir x 2 b x 128 d-groups
    scan_kernel<<<512, blk>>>(dtuz, xdbl, A_log[0], A_log[1],
                              Dp[0], Dp[1], yhi, ylo);

    // out-proj (both dirs via z)
    mma_gemm2<<<dim3(8, 32, 2), blk, DSMEM2>>>(
        yhi, ylo, DIN, outwhi, outwlo, DIN,
        nullptr, nullptr, ydir, nullptr, nullptr,
        DM, DIN, 0, szXC, szOUTW, szYDIR);

    // fused residual + LN
    resln_kernel<<<ML, blk>>>(x, ydir, ydir + szYDIR, ff_ln_g, ff_ln_b,
                              xsum, lnhi, lnlo);

    // ff1 = silu(ln @ ff_w1^T + b1) -> bf16 hi/lo
    mma_gemm2<<<dim3(32, 32, 1), blk, DSMEM2>>>(
        lnhi, lnlo, DM, w1hi, w1lo, DM,
        ff_b1, nullptr, nullptr, f1hi, f1lo,
        DFF, DM, 1, 0, 0, 0);

    // out = xsum + (ff1 @ ff_w2^T + b2)
    mma_gemm2<<<dim3(8, 32, 1), blk, DSMEM2>>>(
        f1hi, f1lo, DFF, w2hi, w2lo, DFF,
        ff_b2, xsum, (float*)d_out, nullptr, nullptr,
        DM, DFF, 0, 0, 0, 0);
}

// round 8
// speedup vs baseline: 1.0034x; 1.0034x over previous
#include <cuda_runtime.h>
#include <cuda_bf16.h>
#include <math.h>
#include <stdint.h>

// Problem constants
#define BB   2
#define LS   2048
#define DM   1024
#define DIN  2048
#define DST  16
#define RDT  64
#define ML   (BB*LS)      // 4096 rows
#define DFF  (4*DM)       // 4096

typedef __nv_bfloat16 bf16;

// ---------------- scratch (device globals) -----------------------------------
// xz unified: [ML][8192], cols [dir*4096 .. +2047]=xi, [+2048..+4095]=z
__device__ __align__(256) float g_xz  [(size_t)ML * 8192];
__device__ __align__(256) float g_xc  [2u * ML * DIN];
__device__ __align__(256) float g_xdbl[2u * ML * 96];     // cols 64..95: B/C interleaved
__device__ __align__(256) float g_dtu [2u * (size_t)ML * DIN * 2];  // (dt, u) pairs
__device__ __align__(256) float g_ydir[2u * ML * DM];
__device__ __align__(256) float g_xsum[(size_t)ML * DM];

__device__ __align__(256) bf16 g_xhi [(size_t)ML * DM],  g_xlo [(size_t)ML * DM];
__device__ __align__(256) bf16 g_yhi [2u * ML * DIN],    g_ylo [2u * ML * DIN];
__device__ __align__(256) bf16 g_lnhi[(size_t)ML * DM],  g_lnlo[(size_t)ML * DM];
__device__ __align__(256) bf16 g_f1hi[(size_t)ML * DFF], g_f1lo[(size_t)ML * DFF];
__device__ __align__(256) bf16 g_inwhi [2u * 2 * DIN * DM], g_inwlo [2u * 2 * DIN * DM];
__device__ __align__(256) bf16 g_outwhi[2u * DM * DIN],     g_outwlo[2u * DM * DIN];
__device__ __align__(256) bf16 g_w1hi[(size_t)DFF * DM],  g_w1lo[(size_t)DFF * DM];
__device__ __align__(256) bf16 g_w2hi[(size_t)DM * DFF],  g_w2lo[(size_t)DM * DFF];

// ---------------- helpers ------------------------------------------------------
__device__ __forceinline__ float siluf(float v) { return v / (1.f + __expf(-v)); }
__device__ __forceinline__ float softplusf(float v) {
    return (v > 20.f) ? v : log1pf(__expf(v));
}
__device__ __forceinline__ void split1(float f, unsigned short& h, unsigned short& l) {
    __nv_bfloat16 hb = __float2bfloat16(f);
    h = __bfloat16_as_ushort(hb);
    l = __bfloat16_as_ushort(__float2bfloat16(f - __bfloat162float(hb)));
}

#define LDSM4(r0, r1, r2, r3, addr) \
    asm volatile("ldmatrix.sync.aligned.m8n8.x4.shared.b16 {%0,%1,%2,%3}, [%4];" \
        : "=r"(r0), "=r"(r1), "=r"(r2), "=r"(r3) : "r"(addr))

#define MMA16816(d, a, b0, b1) \
    asm volatile("mma.sync.aligned.m16n8k16.row.col.f32.bf16.bf16.f32 " \
        "{%0,%1,%2,%3}, {%4,%5,%6,%7}, {%8,%9}, {%0,%1,%2,%3};" \
        : "+f"((d)[0]), "+f"((d)[1]), "+f"((d)[2]), "+f"((d)[3]) \
        : "r"((a)[0]), "r"((a)[1]), "r"((a)[2]), "r"((a)[3]), "r"(b0), "r"(b1))

#define CPA16(sa, ga) \
    asm volatile("cp.async.cg.shared.global [%0], [%1], 16;" :: "r"(sa), "l"(ga))
#define CPA_COMMIT() asm volatile("cp.async.commit_group;" ::: "memory")
#define CPA_WAIT1()  asm volatile("cp.async.wait_group 1;" ::: "memory")
#define CPA_WAIT0()  asm volatile("cp.async.wait_group 0;" ::: "memory")

// ---------------- split-bf16 tensor-core GEMM, persistent tile loop ------------
#define KC       32
#define ARR_B    8192
#define STAGE_B  (4 * ARR_B)
#define NSTAGE   3
#define DSMEM2   (NSTAGE * STAGE_B)
#define GEMM_GRID 296

__global__ __launch_bounds__(256, 2)
void mma_gemm2(const bf16* __restrict__ Ahi, const bf16* __restrict__ Alo, int lda,
               const bf16* __restrict__ Bhi, const bf16* __restrict__ Blo, int ldb,
               const float* __restrict__ bias,
               const float* __restrict__ addsrc,
               float* __restrict__ Cf,
               bf16* __restrict__ Chi, bf16* __restrict__ Clo,
               int ldc, int K, int act,
               size_t zsA, size_t zsB, size_t zsC,
               int gx, int gy, int gz)
{
    extern __shared__ char sm[];
    const int tid  = threadIdx.x;
    const int lane = tid & 31;
    const int wid  = tid >> 5;
    const int wm   = wid >> 2;
    const int wn   = wid & 3;
    const uint32_t smb = (uint32_t)__cvta_generic_to_shared(sm);

    const int crow = tid >> 2;
    const int cck  = tid & 3;
    const uint32_t s0 = (uint32_t)crow * 64        + (uint32_t)((cck ^ ((crow >> 1) & 3)) * 16);
    const uint32_t s1 = (uint32_t)(crow + 64) * 64 + (uint32_t)((cck ^ (((crow + 64) >> 1) & 3)) * 16);

    const int laneAr = (lane & 7) + ((lane >> 3) & 1) * 8;
    const int aCk    = (lane >> 4);
    const int laneBr = (lane & 7) + ((lane >> 4) & 1) * 8;
    const int bCk    = (lane >> 3) & 1;
    uint32_t aRowB[4], aSw[4], bRowB[2], bSw[2];
    #pragma unroll
    for (int i = 0; i < 4; i++) {
        int r = wm * 64 + i * 16 + laneAr;
        aRowB[i] = (uint32_t)r * 64;
        aSw[i]   = (uint32_t)((r >> 1) & 3);
    }
    #pragma unroll
    for (int p = 0; p < 2; p++) {
        int r = wn * 32 + p * 16 + laneBr;
        bRowB[p] = (uint32_t)r * 64;
        bSw[p]   = (uint32_t)((r >> 1) & 3);
    }

    const int nk = K / KC;
    const int ntiles = gx * gy * gz;

    for (int t = blockIdx.x; t < ntiles; t += gridDim.x) {
        const int tz  = t / (gx * gy);
        const int rem = t - tz * gx * gy;
        const int tyy = rem / gx;
        const int txx = rem - tyy * gx;
        const int rowBase = tyy * 128;
        const int colBase = txx * 128;
        const size_t zA = (size_t)tz * zsA;
        const size_t zB = (size_t)tz * zsB;
        const size_t zC = (size_t)tz * zsC;

        const size_t offA0 = zA + (size_t)(rowBase + crow) * lda + cck * 8;
        const size_t offA1 = zA + (size_t)(rowBase + crow + 64) * lda + cck * 8;
        const size_t offB0 = zB + (size_t)(colBase + crow) * ldb + cck * 8;
        const size_t offB1 = zB + (size_t)(colBase + crow + 64) * ldb + cck * 8;

        float acc[16][4];
        #pragma unroll
        for (int i = 0; i < 16; i++)
            #pragma unroll
            for (int j = 0; j < 4; j++) acc[i][j] = 0.f;

        auto issue = [&](int stg, int kt) {
            const uint32_t sb = smb + (uint32_t)stg * STAGE_B;
            const size_t ko = (size_t)kt * KC;
            CPA16(sb + 0*ARR_B + s0, Ahi + offA0 + ko);
            CPA16(sb + 0*ARR_B + s1, Ahi + offA1 + ko);
            CPA16(sb + 1*ARR_B + s0, Alo + offA0 + ko);
            CPA16(sb + 1*ARR_B + s1, Alo + offA1 + ko);
            CPA16(sb + 2*ARR_B + s0, Bhi + offB0 + ko);
            CPA16(sb + 2*ARR_B + s1, Bhi + offB1 + ko);
            CPA16(sb + 3*ARR_B + s0, Blo + offB0 + ko);
            CPA16(sb + 3*ARR_B + s1, Blo + offB1 + ko);
        };

        issue(0, 0); CPA_COMMIT();
        issue(1, 1); CPA_COMMIT();

        int stg = 0;
        for (int kt = 0; kt < nk; kt++) {
            CPA_WAIT1();
            __syncthreads();
            if (kt + 2 < nk) issue((stg + 2) % NSTAGE, kt + 2);
            CPA_COMMIT();

            const uint32_t base = smb + (uint32_t)stg * STAGE_B;
            #pragma unroll
            for (int ks = 0; ks < 2; ks++) {
                uint32_t aH[4][4], aL[4][4], bH[2][4], bL[2][4];
                #pragma unroll
                for (int i = 0; i < 4; i++)
                    LDSM4(aH[i][0], aH[i][1], aH[i][2], aH[i][3],
                          base + 0*ARR_B + aRowB[i] + (((uint32_t)(ks*2 + aCk) ^ aSw[i]) * 16));
                #pragma unroll
                for (int p = 0; p < 2; p++)
                    LDSM4(bH[p][0], bH[p][1], bH[p][2], bH[p][3],
                          base + 2*ARR_B + bRowB[p] + (((uint32_t)(ks*2 + bCk) ^ bSw[p]) * 16));
                #pragma unroll
                for (int i = 0; i < 4; i++)
                    #pragma unroll
                    for (int nt = 0; nt < 4; nt++)
                        MMA16816(acc[i*4+nt], aH[i], bH[nt>>1][(nt&1)*2], bH[nt>>1][(nt&1)*2+1]);
                #pragma unroll
                for (int i = 0; i < 4; i++)
                    LDSM4(aL[i][0], aL[i][1], aL[i][2], aL[i][3],
                          base + 1*ARR_B + aRowB[i] + (((uint32_t)(ks*2 + aCk) ^ aSw[i]) * 16));
                #pragma unroll
                for (int i = 0; i < 4; i++)
                    #pragma unroll
                    for (int nt = 0; nt < 4; nt++)
                        MMA16816(acc[i*4+nt], aL[i], bH[nt>>1][(nt&1)*2], bH[nt>>1][(nt&1)*2+1]);
                #pragma unroll
                for (int p = 0; p < 2; p++)
                    LDSM4(bL[p][0], bL[p][1], bL[p][2], bL[p][3],
                          base + 3*ARR_B + bRowB[p] + (((uint32_t)(ks*2 + bCk) ^ bSw[p]) * 16));
                #pragma unroll
                for (int i = 0; i < 4; i++)
                    #pragma unroll
                    for (int nt = 0; nt < 4; nt++)
                        MMA16816(acc[i*4+nt], aH[i], bL[nt>>1][(nt&1)*2], bL[nt>>1][(nt&1)*2+1]);
            }
            stg = (stg + 1) % NSTAGE;
        }
        // drain remaining async copies before next tile reuses buffers
        CPA_WAIT0();

        const int erow  = wm * 64 + (lane >> 2);
        const int ecol0 = wn * 32 + (lane & 3) * 2;
        #pragma unroll
        for (int i = 0; i < 4; i++) {
            int r0 = rowBase + erow + i * 16;
            int r1 = r0 + 8;
            #pragma unroll
            for (int nt = 0; nt < 4; nt++) {
                int c = colBase + ecol0 + nt * 8;
                float v0 = acc[i*4+nt][0], v1 = acc[i*4+nt][1];
                float v2 = acc[i*4+nt][2], v3 = acc[i*4+nt][3];
                if (bias) {
                    float b0 = __ldg(&bias[c]), b1 = __ldg(&bias[c+1]);
                    v0 += b0; v1 += b1; v2 += b0; v3 += b1;
                }
                if (act == 1) { v0 = siluf(v0); v1 = siluf(v1); v2 = siluf(v2); v3 = siluf(v3); }
                else if (act == 2) { v0 = softplusf(v0); v1 = softplusf(v1); v2 = softplusf(v2); v3 = softplusf(v3); }
                if (addsrc) {
                    v0 += addsrc[(size_t)r0 * ldc + c];
                    v1 += addsrc[(size_t)r0 * ldc + c + 1];
                    v2 += addsrc[(size_t)r1 * ldc + c];
                    v3 += addsrc[(size_t)r1 * ldc + c + 1];
                }
                if (Cf) {
                    *(float2*)&Cf[zC + (size_t)r0 * ldc + c] = make_float2(v0, v1);
                    *(float2*)&Cf[zC + (size_t)r1 * ldc + c] = make_float2(v2, v3);
                } else {
                    unsigned short h0,h1,h2,h3,l0,l1,l2,l3;
                    split1(v0, h0, l0); split1(v1, h1, l1);
                    split1(v2, h2, l2); split1(v3, h3, l3);
                    *(uint32_t*)(Chi + zC + (size_t)r0 * ldc + c) = (uint32_t)h0 | ((uint32_t)h1 << 16);
                    *(uint32_t*)(Clo + zC + (size_t)r0 * ldc + c) = (uint32_t)l0 | ((uint32_t)l1 << 16);
                    *(uint32_t*)(Chi + zC + (size_t)r1 * ldc + c) = (uint32_t)h2 | ((uint32_t)h3 << 16);
                    *(uint32_t*)(Clo + zC + (size_t)r1 * ldc + c) = (uint32_t)l2 | ((uint32_t)l3 << 16);
                }
            }
        }
        __syncthreads();   // protect smem reuse across tile iterations
    }
}

// ---------------- fp32 -> bf16 hi/lo split --------------------------------------
__global__ void split_kernel(const float* __restrict__ in,
                             bf16* __restrict__ hi,
                             bf16* __restrict__ lo, int n4)
{
    int i = blockIdx.x * blockDim.x + threadIdx.x;
    if (i >= n4) return;
    float4 v = ((const float4*)in)[i];
    unsigned short h0,h1,h2,h3,l0,l1,l2,l3;
    split1(v.x, h0, l0); split1(v.y, h1, l1);
    split1(v.z, h2, l2); split1(v.w, h3, l3);
    uint2 hu, lu;
    hu.x = (uint32_t)h0 | ((uint32_t)h1 << 16);
    hu.y = (uint32_t)h2 | ((uint32_t)h3 << 16);
    lu.x = (uint32_t)l0 | ((uint32_t)l1 << 16);
    lu.y = (uint32_t)l2 | ((uint32_t)l3 << 16);
    *(uint2*)(hi + (size_t)i * 4) = hu;
    *(uint2*)(lo + (size_t)i * 4) = lu;
}

// ---------------- xdbl GEMM: [2][ML][96], B/C interleaved in cols 64..95 --------
__global__ __launch_bounds__(128)
void xdbl_gemm(const float* __restrict__ xcA,
               const float* __restrict__ xw0,
               const float* __restrict__ xw1,
               float* __restrict__ out)
{
    __shared__ float As[16][36];
    __shared__ float Bs[16][100];
    const int dir = blockIdx.z;
    const float* A = xcA + (size_t)dir * ML * DIN + (size_t)blockIdx.x * 32 * DIN;
    const float* B = dir ? xw1 : xw0;
    float* C = out + (size_t)dir * ML * 96 + (size_t)blockIdx.x * 32 * 96;

    const int tid = threadIdx.x;
    const int tx = tid & 15, ty = tid >> 4;
    float acc[4][6];
    #pragma unroll
    for (int i = 0; i < 4; i++)
        #pragma unroll
        for (int j = 0; j < 6; j++) acc[i][j] = 0.f;

    const int ar = tid >> 2, akc = (tid & 3) * 4;

    for (int k0 = 0; k0 < DIN; k0 += 16) {
        {
            float4 v = *(const float4*)(A + (size_t)ar * DIN + k0 + akc);
            As[akc+0][ar] = v.x; As[akc+1][ar] = v.y;
            As[akc+2][ar] = v.z; As[akc+3][ar] = v.w;
        }
        #pragma unroll
        for (int j = 0; j < 3; j++) {
            int i = tid + j * 128;
            int n = i >> 2, kc = (i & 3) * 4;
            float4 v = *(const float4*)(B + (size_t)n * DIN + k0 + kc);
            Bs[kc+0][n] = v.x; Bs[kc+1][n] = v.y;
            Bs[kc+2][n] = v.z; Bs[kc+3][n] = v.w;
        }
        __syncthreads();
        #pragma unroll
        for (int kk = 0; kk < 16; kk++) {
            float4 a4 = *(const float4*)&As[kk][ty*4];
            float ar4[4] = {a4.x, a4.y, a4.z, a4.w};
            float2 b0 = *(const float2*)&Bs[kk][tx*6];
            float2 b1 = *(const float2*)&Bs[kk][tx*6+2];
            float2 b2 = *(const float2*)&Bs[kk][tx*6+4];
            float br[6] = {b0.x, b0.y, b1.x, b1.y, b2.x, b2.y};
            #pragma unroll
            for (int i = 0; i < 4; i++)
                #pragma unroll
                for (int j = 0; j < 6; j++)
                    acc[i][j] = fmaf(ar4[i], br[j], acc[i][j]);
        }
        __syncthreads();
    }
    #pragma unroll
    for (int i = 0; i < 4; i++)
        #pragma unroll
        for (int j = 0; j < 6; j++) {
            int c = tx*6 + j;
            int cw = (c < 64) ? c : ((c < 80) ? (64 + 2*(c - 64)) : (65 + 2*(c - 80)));
            C[(size_t)(ty*4+i) * 96 + cw] = acc[i][j];
        }
}

// ---------------- dt GEMM -> (dt, u) float2 pairs --------------------------------
__global__ __launch_bounds__(256)
void dt_gemm(const float* __restrict__ xdblA,
             const float* __restrict__ xcA,
             const float* __restrict__ w0, const float* __restrict__ w1,
             const float* __restrict__ b0, const float* __restrict__ b1,
             float* __restrict__ out)          // [2][ML][DIN][2]
{
    __shared__ float As[16][132];
    __shared__ float Bs[16][132];

    const int dir = blockIdx.z;
    const float* A = xdblA + (size_t)dir * ML * 96;
    const float* xcD = xcA + (size_t)dir * ML * DIN;
    const float* Bw = dir ? w1 : w0;
    const float* bias = dir ? b1 : b0;
    float* C = out + (size_t)dir * ML * DIN * 2;

    const int tid = threadIdx.x;
    const int tx = tid & 15;
    const int ty = tid >> 4;
    const int rowBase = blockIdx.y * 128;
    const int colBase = blockIdx.x * 128;

    const int lm = tid >> 1;
    const int lk = (tid & 1) * 8;

    const float* aPtr = A + (size_t)(rowBase + lm) * 96 + lk;
    const float* bPtr = Bw + (size_t)(colBase + lm) * RDT + lk;

    float acc[8][8];
    #pragma unroll
    for (int i = 0; i < 8; i++)
        #pragma unroll
        for (int j = 0; j < 8; j++) acc[i][j] = 0.f;

    for (int k0 = 0; k0 < RDT; k0 += 16) {
        float4 a0 = *(const float4*)(aPtr + k0);
        float4 a1 = *(const float4*)(aPtr + k0 + 4);
        float4 b0v = *(const float4*)(bPtr + k0);
        float4 b1v = *(const float4*)(bPtr + k0 + 4);

        As[lk+0][lm] = a0.x; As[lk+1][lm] = a0.y; As[lk+2][lm] = a0.z; As[lk+3][lm] = a0.w;
        As[lk+4][lm] = a1.x; As[lk+5][lm] = a1.y; As[lk+6][lm] = a1.z; As[lk+7][lm] = a1.w;
        Bs[lk+0][lm] = b0v.x; Bs[lk+1][lm] = b0v.y; Bs[lk+2][lm] = b0v.z; Bs[lk+3][lm] = b0v.w;
        Bs[lk+4][lm] = b1v.x; Bs[lk+5][lm] = b1v.y; Bs[lk+6][lm] = b1v.z; Bs[lk+7][lm] = b1v.w;
        __syncthreads();

        #pragma unroll
        for (int kk = 0; kk < 16; kk++) {
            float4 ra0 = *(const float4*)&As[kk][ty * 4];
            float4 ra1 = *(const float4*)&As[kk][64 + ty * 4];
            float4 rb0 = *(const float4*)&Bs[kk][tx * 4];
            float4 rb1 = *(const float4*)&Bs[kk][64 + tx * 4];
            float ar[8] = {ra0.x, ra0.y, ra0.z, ra0.w, ra1.x, ra1.y, ra1.z, ra1.w};
            float br[8] = {rb0.x, rb0.y, rb0.z, rb0.w, rb1.x, rb1.y, rb1.z, rb1.w};
            #pragma unroll
            for (int i = 0; i < 8; i++)
                #pragma unroll
                for (int j = 0; j < 8; j++)
                    acc[i][j] = fmaf(ar[i], br[j], acc[i][j]);
        }
        __syncthreads();
    }

    #pragma unroll
    for (int i = 0; i < 8; i++) {
        int r = rowBase + ((i < 4) ? (ty * 4 + i) : (64 + ty * 4 + i - 4));
        #pragma unroll
        for (int j = 0; j < 8; j++) {
            int c = colBase + ((j < 4) ? (tx * 4 + j) : (64 + tx * 4 + j - 4));
            float dtv = softplusf(acc[i][j] + bias[c]);
            float uv  = xcD[(size_t)r * DIN + c];
            *(float2*)&C[((size_t)r * DIN + c) * 2] = make_float2(dtv, uv);
        }
    }
}

// ---------------- depthwise causal conv (k=4, dir-dependent taps) ---------------
__global__ void conv_kernel(const float* __restrict__ xz,
                            const float* __restrict__ cw0, const float* __restrict__ cw1,
                            const float* __restrict__ cb0, const float* __restrict__ cb1,
                            float* __restrict__ xc)
{
    int idx = blockIdx.x * blockDim.x + threadIdx.x;
    if (idx >= 2 * ML * DIN) return;
    int dir = idx >= ML * DIN;
    int li = dir ? (idx - ML * DIN) : idx;
    int c = li & (DIN - 1);
    int r = li / DIN;
    int l = r & (LS - 1);
    int b = r >> 11;
    const float* cw = dir ? cw1 : cw0;
    const float* cb = dir ? cb1 : cb0;
    float acc = cb[c];
    float w0 = cw[c*4+0], w1 = cw[c*4+1], w2 = cw[c*4+2], w3 = cw[c*4+3];
    size_t colOff = (size_t)dir * 4096 + c;
    if (!dir) {
        #pragma unroll
        for (int k = 0; k < 4; k++) {
            int lp = l - 3 + k;
            if (lp >= 0) {
                float w = (k==0)?w0:(k==1)?w1:(k==2)?w2:w3;
                acc += xz[(size_t)(b * LS + lp) * 8192 + colOff] * w;
            }
        }
    } else {
        #pragma unroll
        for (int k = 0; k < 4; k++) {
            int lp = l + 3 - k;
            if (lp < LS) {
                float w = (k==0)?w0:(k==1)?w1:(k==2)?w2:w3;
                acc += xz[(size_t)(b * LS + lp) * 8192 + colOff] * w;
            }
        }
    }
    xc[(size_t)dir * ML * DIN + (size_t)r * DIN + c] = siluf(acc);
}

// ---------------- selective scan (packed operands, R6 form) ----------------------
__global__ void scan_kernel(const float* __restrict__ dtu,   // [2][ML][DIN][2]
                            const float* __restrict__ xdbl,  // [2][ML][96] (B/C paired)
                            const float* __restrict__ xz,    // [ML][8192]
                            const float* __restrict__ A0, const float* __restrict__ A1,
                            const float* __restrict__ D0, const float* __restrict__ D1,
                            bf16* __restrict__ yhi, bf16* __restrict__ ylo)
{
    int gwarp = (blockIdx.x * blockDim.x + threadIdx.x) >> 5;
    int lane = threadIdx.x & 31;
    int half = lane >> 4;
    int s = lane & 15;
    int row = gwarp * 2 + half;
    if (row >= 2 * BB * DIN) return;
    int dir = row >= BB * DIN;
    int r2 = dir ? (row - BB * DIN) : row;
    int b = r2 / DIN;
    int d = r2 % DIN;

    const float* Alog = dir ? A1 : A0;
    float Av = -__expf(Alog[d * DST + s]);
    float Dd = dir ? D1[d] : D0[d];
    float h = 0.f;
    const bool w0lane = (s == 0);

    const size_t base = (size_t)b * LS;
    const int l0 = dir ? (LS - 1) : 0;
    const int step = dir ? -1 : 1;

    const float* pDtu = dtu + ((size_t)dir * ML * DIN + (base + l0) * DIN + d) * 2;
    const float* pBC  = xdbl + (size_t)dir * ML * 96 + (base + l0) * 96 + RDT + 2 * s;
    const float* pZ   = xz + (base + l0) * 8192 + (size_t)dir * 4096 + 2048 + d;
    bf16* pYhi = yhi + (size_t)dir * ML * DIN + (base + l0) * DIN + d;
    bf16* pYlo = ylo + (size_t)dir * ML * DIN + (base + l0) * DIN + d;
    const ptrdiff_t sDtu = (ptrdiff_t)step * DIN * 2;
    const ptrdiff_t sBC  = (ptrdiff_t)step * 96;
    const ptrdiff_t sZ   = (ptrdiff_t)step * 8192;
    const ptrdiff_t sY   = (ptrdiff_t)step * DIN;

    float2 du = *(const float2*)pDtu;
    float2 bc = *(const float2*)pBC;
    float zv  = w0lane ? *pZ : 0.f;

    for (int it = 0; it < LS; it++) {
        const bool more = (it + 1 < LS);
        float2 dun = more ? *(const float2*)(pDtu + sDtu) : du;
        float2 bcn = more ? *(const float2*)(pBC + sBC)   : bc;
        float zn   = (w0lane && more) ? *(pZ + sZ) : zv;

        h = h * __expf(du.x * Av) + du.x * du.y * bc.x;
        float y = h * bc.y;
        y += __shfl_xor_sync(0xffffffffu, y, 8);
        y += __shfl_xor_sync(0xffffffffu, y, 4);
        y += __shfl_xor_sync(0xffffffffu, y, 2);
        y += __shfl_xor_sync(0xffffffffu, y, 1);
        if (w0lane) {
            float yv = (y + du.y * Dd) * siluf(zv);
            __nv_bfloat16 hb = __float2bfloat16(yv);
            *pYhi = hb;
            *pYlo = __float2bfloat16(yv - __bfloat162float(hb));
            pYhi += sY; pYlo += sY;
        }
        pDtu += sDtu; pBC += sBC; pZ += sZ;
        du = dun; bc = bcn; zv = zn;
    }
}

// ---------------- fused residual + layernorm -> xsum + bf16 hi/lo ----------------
__global__ void resln_kernel(const float* __restrict__ x,
                             const float* __restrict__ y0,
                             const float* __restrict__ y1,
                             const float* __restrict__ g,
                             const float* __restrict__ bta,
                             float* __restrict__ xsum,
                             bf16* __restrict__ outhi,
                             bf16* __restrict__ outlo)
{
    int row = blockIdx.x;
    size_t off4 = (size_t)row * (DM / 4) + threadIdx.x;
    float4 xv = ((const float4*)x)[off4];
    float4 a = ((const float4*)y0)[off4];
    float4 b = ((const float4*)y1)[off4];
    float4 v;
    v.x = xv.x + 0.5f * (a.x + b.x);
    v.y = xv.y + 0.5f * (a.y + b.y);
    v.z = xv.z + 0.5f * (a.z + b.z);
    v.w = xv.w + 0.5f * (a.w + b.w);
    ((float4*)xsum)[off4] = v;

    float s  = v.x + v.y + v.z + v.w;
    float sq = v.x*v.x + v.y*v.y + v.z*v.z + v.w*v.w;
    #pragma unroll
    for (int o = 16; o >= 1; o >>= 1) {
        s  += __shfl_xor_sync(0xffffffffu, s, o);
        sq += __shfl_xor_sync(0xffffffffu, sq, o);
    }
    __shared__ float ss[8], ssq[8];
    int warp = threadIdx.x >> 5, lane = threadIdx.x & 31;
    if (lane == 0) { ss[warp] = s; ssq[warp] = sq; }
    __syncthreads();
    __shared__ float sh_mean, sh_inv;
    if (threadIdx.x == 0) {
        float ts = 0.f, tq = 0.f;
        #pragma unroll
        for (int w = 0; w < 8; w++) { ts += ss[w]; tq += ssq[w]; }
        float mean = ts / DM;
        float var = tq / DM - mean * mean;
        sh_mean = mean;
        sh_inv = rsqrtf(var + 1e-5f);
    }
    __syncthreads();
    float mean = sh_mean, inv = sh_inv;
    float4 gv = ((const float4*)g)[threadIdx.x];
    float4 bv = ((const float4*)bta)[threadIdx.x];
    float o0 = (v.x - mean) * inv * gv.x + bv.x;
    float o1 = (v.y - mean) * inv * gv.y + bv.y;
    float o2 = (v.z - mean) * inv * gv.z + bv.z;
    float o3 = (v.w - mean) * inv * gv.w + bv.w;
    unsigned short h0,h1,h2,h3,l0,l1,l2,l3;
    split1(o0, h0, l0); split1(o1, h1, l1);
    split1(o2, h2, l2); split1(o3, h3, l3);
    uint2 hu, lu;
    hu.x = (uint32_t)h0 | ((uint32_t)h1 << 16);
    hu.y = (uint32_t)h2 | ((uint32_t)h3 << 16);
    lu.x = (uint32_t)l0 | ((uint32_t)l1 << 16);
    lu.y = (uint32_t)l2 | ((uint32_t)l3 << 16);
    size_t off = (size_t)row * DM + threadIdx.x * 4;
    *(uint2*)(outhi + off) = hu;
    *(uint2*)(outlo + off) = lu;
}

// ---------------- host orchestration ----------------------------------------------
extern "C" void kernel_launch(void* const* d_in, const int* in_sizes, int n_in,
                              void* d_out, int out_size)
{
    (void)in_sizes; (void)n_in; (void)out_size;

    const float* x = (const float*)d_in[0];
    const float* in_w[2]   = { (const float*)d_in[1],  (const float*)d_in[10] };
    const float* conv_w[2] = { (const float*)d_in[2],  (const float*)d_in[11] };
    const float* conv_b[2] = { (const float*)d_in[3],  (const float*)d_in[12] };
    const float* x_w[2]    = { (const float*)d_in[4],  (const float*)d_in[13] };
    const float* dt_w[2]   = { (const float*)d_in[5],  (const float*)d_in[14] };
    const float* dt_b[2]   = { (const float*)d_in[6],  (const float*)d_in[15] };
    const float* A_log[2]  = { (const float*)d_in[7],  (const float*)d_in[16] };
    const float* Dp[2]     = { (const float*)d_in[8],  (const float*)d_in[17] };
    const float* out_w[2]  = { (const float*)d_in[9],  (const float*)d_in[18] };
    const float* ff_ln_g = (const float*)d_in[19];
    const float* ff_ln_b = (const float*)d_in[20];
    const float* ff_w1   = (const float*)d_in[21];
    const float* ff_b1   = (const float*)d_in[22];
    const float* ff_w2   = (const float*)d_in[23];
    const float* ff_b2   = (const float*)d_in[24];

    float *xz, *xc, *xdbl, *dtu, *ydir, *xsum;
    bf16 *xhi, *xlo, *yhi, *ylo, *lnhi, *lnlo, *f1hi, *f1lo;
    bf16 *inwhi, *inwlo, *outwhi, *outwlo, *w1hi, *w1lo, *w2hi, *w2lo;
    cudaGetSymbolAddress((void**)&xz,   g_xz);
    cudaGetSymbolAddress((void**)&xc,   g_xc);
    cudaGetSymbolAddress((void**)&xdbl, g_xdbl);
    cudaGetSymbolAddress((void**)&dtu,  g_dtu);
    cudaGetSymbolAddress((void**)&ydir, g_ydir);
    cudaGetSymbolAddress((void**)&xsum, g_xsum);
    cudaGetSymbolAddress((void**)&xhi,  g_xhi);
    cudaGetSymbolAddress((void**)&xlo,  g_xlo);
    cudaGetSymbolAddress((void**)&yhi,  g_yhi);
    cudaGetSymbolAddress((void**)&ylo,  g_ylo);
    cudaGetSymbolAddress((void**)&lnhi, g_lnhi);
    cudaGetSymbolAddress((void**)&lnlo, g_lnlo);
    cudaGetSymbolAddress((void**)&f1hi, g_f1hi);
    cudaGetSymbolAddress((void**)&f1lo, g_f1lo);
    cudaGetSymbolAddress((void**)&inwhi,  g_inwhi);
    cudaGetSymbolAddress((void**)&inwlo,  g_inwlo);
    cudaGetSymbolAddress((void**)&outwhi, g_outwhi);
    cudaGetSymbolAddress((void**)&outwlo, g_outwlo);
    cudaGetSymbolAddress((void**)&w1hi, g_w1hi);
    cudaGetSymbolAddress((void**)&w1lo, g_w1lo);
    cudaGetSymbolAddress((void**)&w2hi, g_w2hi);
    cudaGetSymbolAddress((void**)&w2lo, g_w2lo);

    cudaFuncSetAttribute(mma_gemm2, cudaFuncAttributeMaxDynamicSharedMemorySize, DSMEM2);

    const size_t szXC   = (size_t)ML * DIN;
    const size_t szYDIR = (size_t)ML * DM;
    const size_t szINW  = (size_t)2 * DIN * DM;
    const size_t szOUTW = (size_t)DM * DIN;

    dim3 blk(256);

    // idx 0-2: splits needed for in-proj
    split_kernel<<<(ML*DM/4 + 255)/256, blk>>>(x, xhi, xlo, ML*DM/4);
    split_kernel<<<((int)szINW/4 + 255)/256, blk>>>(in_w[0], inwhi,         inwlo,         (int)szINW/4);
    split_kernel<<<((int)szINW/4 + 255)/256, blk>>>(in_w[1], inwhi + szINW, inwlo + szINW, (int)szINW/4);

    // idx 3 (profiled): merged in-proj, M=4096, N=8192, K=1024, persistent tiles
    mma_gemm2<<<GEMM_GRID, blk, DSMEM2>>>(
        xhi, xlo, DM, inwhi, inwlo, DM,
        nullptr, nullptr, xz, nullptr, nullptr,
        8192, DM, 0, 0, 0, 0, 64, 32, 1);

    // remaining splits
    split_kernel<<<(DFF*DM/4 + 255)/256, blk>>>(ff_w1, w1hi, w1lo, DFF*DM/4);
    split_kernel<<<((int)szOUTW/4 + 255)/256, blk>>>(out_w[0], outwhi,          outwlo,          (int)szOUTW/4);
    split_kernel<<<((int)szOUTW/4 + 255)/256, blk>>>(out_w[1], outwhi + szOUTW, outwlo + szOUTW, (int)szOUTW/4);
    split_kernel<<<(DM*DFF/4 + 255)/256, blk>>>(ff_w2, w2hi, w2lo, DM*DFF/4);

    // conv (both dirs)
    conv_kernel<<<(2*ML*DIN + 255)/256, blk>>>(xz, conv_w[0], conv_w[1],
                                               conv_b[0], conv_b[1], xc);

    // xdbl (both dirs), B/C interleaved
    xdbl_gemm<<<dim3(ML/32, 1, 2), dim3(128)>>>(xc, x_w[0], x_w[1], xdbl);

    // dt (both dirs) -> (dt, u) pairs
    dt_gemm<<<dim3(DIN/128, ML/128, 2), blk>>>(xdbl, xc, dt_w[0], dt_w[1],
                                               dt_b[0], dt_b[1], dtu);

    // scan (both dirs)
    scan_kernel<<<512, blk>>>(dtu, xdbl, xz, A_log[0], A_log[1],
                              Dp[0], Dp[1], yhi, ylo);

    // out-proj (both dirs via tz): ydir[z] = y[z] @ out_w[z]^T
    mma_gemm2<<<GEMM_GRID, blk, DSMEM2>>>(
        yhi, ylo, DIN, outwhi, outwlo, DIN,
        nullptr, nullptr, ydir, nullptr, nullptr,
        DM, DIN, 0, szXC, szOUTW, szYDIR, 8, 32, 2);

    // fused residual + LN
    resln_kernel<<<ML, blk>>>(x, ydir, ydir + szYDIR, ff_ln_g, ff_ln_b,
                              xsum, lnhi, lnlo);

    // ff1 = silu(ln @ ff_w1^T + b1) -> bf16 hi/lo
    mma_gemm2<<<GEMM_GRID, blk, DSMEM2>>>(
        lnhi, lnlo, DM, w1hi, w1lo, DM,
        ff_b1, nullptr, nullptr, f1hi, f1lo,
        DFF, DM, 1, 0, 0, 0, 32, 32, 1);

    // out = xsum + (ff1 @ ff_w2^T + b2)
    mma_gemm2<<<GEMM_GRID, blk, DSMEM2>>>(
        f1hi, f1lo, DFF, w2hi, w2lo, DFF,
        ff_b2, xsum, (float*)d_out, nullptr, nullptr,
        DM, DFF, 0, 0, 0, 0, 8, 32, 1);
}

// round 9
// speedup vs baseline: 1.0236x; 1.0201x over previous
#include <cuda_runtime.h>
#include <cuda_bf16.h>
#include <math.h>
#include <stdint.h>

// Problem constants
#define BB   2
#define LS   2048
#define DM   1024
#define DIN  2048
#define DST  16
#define RDT  64
#define ML   (BB*LS)      // 4096 rows
#define DFF  (4*DM)       // 4096

typedef __nv_bfloat16 bf16;

// ---------------- scratch (device globals) -----------------------------------
// xz unified: [ML][8192], cols [dir*4096 .. +2047]=xi, [+2048..+4095]=z
__device__ __align__(256) float g_xz  [(size_t)ML * 8192];
__device__ __align__(256) float g_xc  [2u * ML * DIN];
__device__ __align__(256) float g_xdbl[2u * ML * 96];     // cols 64..95: B/C interleaved
__device__ __align__(256) float g_dtu [2u * (size_t)ML * DIN * 2];  // (dt, u) pairs
__device__ __align__(256) float g_ydir[2u * ML * DM];
__device__ __align__(256) float g_xsum[(size_t)ML * DM];

__device__ __align__(256) bf16 g_xhi [(size_t)ML * DM],  g_xlo [(size_t)ML * DM];
__device__ __align__(256) bf16 g_yhi [2u * ML * DIN],    g_ylo [2u * ML * DIN];
__device__ __align__(256) bf16 g_lnhi[(size_t)ML * DM],  g_lnlo[(size_t)ML * DM];
__device__ __align__(256) bf16 g_f1hi[(size_t)ML * DFF], g_f1lo[(size_t)ML * DFF];
__device__ __align__(256) bf16 g_inwhi [2u * 2 * DIN * DM], g_inwlo [2u * 2 * DIN * DM];
__device__ __align__(256) bf16 g_outwhi[2u * DM * DIN],     g_outwlo[2u * DM * DIN];
__device__ __align__(256) bf16 g_w1hi[(size_t)DFF * DM],  g_w1lo[(size_t)DFF * DM];
__device__ __align__(256) bf16 g_w2hi[(size_t)DM * DFF],  g_w2lo[(size_t)DM * DFF];

// ---------------- helpers ------------------------------------------------------
__device__ __forceinline__ float siluf(float v) { return v / (1.f + __expf(-v)); }
__device__ __forceinline__ float softplusf(float v) {
    return (v > 20.f) ? v : log1pf(__expf(v));
}
__device__ __forceinline__ void split1(float f, unsigned short& h, unsigned short& l) {
    __nv_bfloat16 hb = __float2bfloat16(f);
    h = __bfloat16_as_ushort(hb);
    l = __bfloat16_as_ushort(__float2bfloat16(f - __bfloat162float(hb)));
}

#define LDSM4(r0, r1, r2, r3, addr) \
    asm volatile("ldmatrix.sync.aligned.m8n8.x4.shared.b16 {%0,%1,%2,%3}, [%4];" \
        : "=r"(r0), "=r"(r1), "=r"(r2), "=r"(r3) : "r"(addr))

#define MMA16816(d, a, b0, b1) \
    asm volatile("mma.sync.aligned.m16n8k16.row.col.f32.bf16.bf16.f32 " \
        "{%0,%1,%2,%3}, {%4,%5,%6,%7}, {%8,%9}, {%0,%1,%2,%3};" \
        : "+f"((d)[0]), "+f"((d)[1]), "+f"((d)[2]), "+f"((d)[3]) \
        : "r"((a)[0]), "r"((a)[1]), "r"((a)[2]), "r"((a)[3]), "r"(b0), "r"(b1))

#define CPA16(sa, ga) \
    asm volatile("cp.async.cg.shared.global [%0], [%1], 16;" :: "r"(sa), "l"(ga))
#define CPA_COMMIT() asm volatile("cp.async.commit_group;" ::: "memory")
#define CPA_WAIT1()  asm volatile("cp.async.wait_group 1;" ::: "memory")

// ---------------- split-bf16 tensor-core GEMM (R6 form, best measured) ---------
#define KC       32
#define ARR_B    8192
#define STAGE_B  (4 * ARR_B)
#define NSTAGE   3
#define DSMEM2   (NSTAGE * STAGE_B)

__global__ __launch_bounds__(256, 2)
void mma_gemm2(const bf16* __restrict__ Ahi, const bf16* __restrict__ Alo, int lda,
               const bf16* __restrict__ Bhi, const bf16* __restrict__ Blo, int ldb,
               const float* __restrict__ bias,
               const float* __restrict__ addsrc,
               float* __restrict__ Cf,
               bf16* __restrict__ Chi, bf16* __restrict__ Clo,
               int ldc, int K, int act,
               size_t zsA, size_t zsB, size_t zsC)
{
    extern __shared__ char sm[];
    const int tid  = threadIdx.x;
    const int lane = tid & 31;
    const int wid  = tid >> 5;
    const int wm   = wid >> 2;
    const int wn   = wid & 3;
    const int rowBase = blockIdx.y * 128;
    const int colBase = blockIdx.x * 128;
    const size_t zA = (size_t)blockIdx.z * zsA;
    const size_t zB = (size_t)blockIdx.z * zsB;
    const size_t zC = (size_t)blockIdx.z * zsC;
    const uint32_t smb = (uint32_t)__cvta_generic_to_shared(sm);

    const int crow = tid >> 2;
    const int cck  = tid & 3;
    const size_t offA0 = zA + (size_t)(rowBase + crow) * lda + cck * 8;
    const size_t offA1 = zA + (size_t)(rowBase + crow + 64) * lda + cck * 8;
    const size_t offB0 = zB + (size_t)(colBase + crow) * ldb + cck * 8;
    const size_t offB1 = zB + (size_t)(colBase + crow + 64) * ldb + cck * 8;
    const uint32_t s0 = (uint32_t)crow * 64        + (uint32_t)((cck ^ ((crow >> 1) & 3)) * 16);
    const uint32_t s1 = (uint32_t)(crow + 64) * 64 + (uint32_t)((cck ^ (((crow + 64) >> 1) & 3)) * 16);

    const int laneAr = (lane & 7) + ((lane >> 3) & 1) * 8;
    const int aCk    = (lane >> 4);
    const int laneBr = (lane & 7) + ((lane >> 4) & 1) * 8;
    const int bCk    = (lane >> 3) & 1;
    uint32_t aRowB[4], aSw[4], bRowB[2], bSw[2];
    #pragma unroll
    for (int i = 0; i < 4; i++) {
        int r = wm * 64 + i * 16 + laneAr;
        aRowB[i] = (uint32_t)r * 64;
        aSw[i]   = (uint32_t)((r >> 1) & 3);
    }
    #pragma unroll
    for (int p = 0; p < 2; p++) {
        int r = wn * 32 + p * 16 + laneBr;
        bRowB[p] = (uint32_t)r * 64;
        bSw[p]   = (uint32_t)((r >> 1) & 3);
    }

    float acc[16][4];
    #pragma unroll
    for (int i = 0; i < 16; i++)
        #pragma unroll
        for (int j = 0; j < 4; j++) acc[i][j] = 0.f;

    const int nk = K / KC;

    auto issue = [&](int stg, int kt) {
        const uint32_t sb = smb + (uint32_t)stg * STAGE_B;
        const size_t ko = (size_t)kt * KC;
        CPA16(sb + 0*ARR_B + s0, Ahi + offA0 + ko);
        CPA16(sb + 0*ARR_B + s1, Ahi + offA1 + ko);
        CPA16(sb + 1*ARR_B + s0, Alo + offA0 + ko);
        CPA16(sb + 1*ARR_B + s1, Alo + offA1 + ko);
        CPA16(sb + 2*ARR_B + s0, Bhi + offB0 + ko);
        CPA16(sb + 2*ARR_B + s1, Bhi + offB1 + ko);
        CPA16(sb + 3*ARR_B + s0, Blo + offB0 + ko);
        CPA16(sb + 3*ARR_B + s1, Blo + offB1 + ko);
    };

    issue(0, 0); CPA_COMMIT();
    issue(1, 1); CPA_COMMIT();

    int stg = 0;
    for (int kt = 0; kt < nk; kt++) {
        CPA_WAIT1();
        __syncthreads();
        if (kt + 2 < nk) issue((stg + 2) % NSTAGE, kt + 2);
        CPA_COMMIT();

        const uint32_t base = smb + (uint32_t)stg * STAGE_B;
        #pragma unroll
        for (int ks = 0; ks < 2; ks++) {
            uint32_t aH[4][4], aL[4][4], bH[2][4], bL[2][4];
            #pragma unroll
            for (int i = 0; i < 4; i++)
                LDSM4(aH[i][0], aH[i][1], aH[i][2], aH[i][3],
                      base + 0*ARR_B + aRowB[i] + (((uint32_t)(ks*2 + aCk) ^ aSw[i]) * 16));
            #pragma unroll
            for (int p = 0; p < 2; p++)
                LDSM4(bH[p][0], bH[p][1], bH[p][2], bH[p][3],
                      base + 2*ARR_B + bRowB[p] + (((uint32_t)(ks*2 + bCk) ^ bSw[p]) * 16));
            #pragma unroll
            for (int i = 0; i < 4; i++)
                #pragma unroll
                for (int nt = 0; nt < 4; nt++)
                    MMA16816(acc[i*4+nt], aH[i], bH[nt>>1][(nt&1)*2], bH[nt>>1][(nt&1)*2+1]);
            #pragma unroll
            for (int i = 0; i < 4; i++)
                LDSM4(aL[i][0], aL[i][1], aL[i][2], aL[i][3],
                      base + 1*ARR_B + aRowB[i] + (((uint32_t)(ks*2 + aCk) ^ aSw[i]) * 16));
            #pragma unroll
            for (int i = 0; i < 4; i++)
                #pragma unroll
                for (int nt = 0; nt < 4; nt++)
                    MMA16816(acc[i*4+nt], aL[i], bH[nt>>1][(nt&1)*2], bH[nt>>1][(nt&1)*2+1]);
            #pragma unroll
            for (int p = 0; p < 2; p++)
                LDSM4(bL[p][0], bL[p][1], bL[p][2], bL[p][3],
                      base + 3*ARR_B + bRowB[p] + (((uint32_t)(ks*2 + bCk) ^ bSw[p]) * 16));
            #pragma unroll
            for (int i = 0; i < 4; i++)
                #pragma unroll
                for (int nt = 0; nt < 4; nt++)
                    MMA16816(acc[i*4+nt], aH[i], bL[nt>>1][(nt&1)*2], bL[nt>>1][(nt&1)*2+1]);
        }
        stg = (stg + 1) % NSTAGE;
    }

    const int erow  = wm * 64 + (lane >> 2);
    const int ecol0 = wn * 32 + (lane & 3) * 2;
    #pragma unroll
    for (int i = 0; i < 4; i++) {
        int r0 = rowBase + erow + i * 16;
        int r1 = r0 + 8;
        #pragma unroll
        for (int nt = 0; nt < 4; nt++) {
            int c = colBase + ecol0 + nt * 8;
            float v0 = acc[i*4+nt][0], v1 = acc[i*4+nt][1];
            float v2 = acc[i*4+nt][2], v3 = acc[i*4+nt][3];
            if (bias) {
                float b0 = __ldg(&bias[c]), b1 = __ldg(&bias[c+1]);
                v0 += b0; v1 += b1; v2 += b0; v3 += b1;
            }
            if (act == 1) { v0 = siluf(v0); v1 = siluf(v1); v2 = siluf(v2); v3 = siluf(v3); }
            else if (act == 2) { v0 = softplusf(v0); v1 = softplusf(v1); v2 = softplusf(v2); v3 = softplusf(v3); }
            if (addsrc) {
                v0 += addsrc[(size_t)r0 * ldc + c];
                v1 += addsrc[(size_t)r0 * ldc + c + 1];
                v2 += addsrc[(size_t)r1 * ldc + c];
                v3 += addsrc[(size_t)r1 * ldc + c + 1];
            }
            if (Cf) {
                *(float2*)&Cf[zC + (size_t)r0 * ldc + c] = make_float2(v0, v1);
                *(float2*)&Cf[zC + (size_t)r1 * ldc + c] = make_float2(v2, v3);
            } else {
                unsigned short h0,h1,h2,h3,l0,l1,l2,l3;
                split1(v0, h0, l0); split1(v1, h1, l1);
                split1(v2, h2, l2); split1(v3, h3, l3);
                *(uint32_t*)(Chi + zC + (size_t)r0 * ldc + c) = (uint32_t)h0 | ((uint32_t)h1 << 16);
                *(uint32_t*)(Clo + zC + (size_t)r0 * ldc + c) = (uint32_t)l0 | ((uint32_t)l1 << 16);
                *(uint32_t*)(Chi + zC + (size_t)r1 * ldc + c) = (uint32_t)h2 | ((uint32_t)h3 << 16);
                *(uint32_t*)(Clo + zC + (size_t)r1 * ldc + c) = (uint32_t)l2 | ((uint32_t)l3 << 16);
            }
        }
    }
}

// ---------------- fp32 -> bf16 hi/lo split --------------------------------------
__global__ void split_kernel(const float* __restrict__ in,
                             bf16* __restrict__ hi,
                             bf16* __restrict__ lo, int n4)
{
    int i = blockIdx.x * blockDim.x + threadIdx.x;
    if (i >= n4) return;
    float4 v = ((const float4*)in)[i];
    unsigned short h0,h1,h2,h3,l0,l1,l2,l3;
    split1(v.x, h0, l0); split1(v.y, h1, l1);
    split1(v.z, h2, l2); split1(v.w, h3, l3);
    uint2 hu, lu;
    hu.x = (uint32_t)h0 | ((uint32_t)h1 << 16);
    hu.y = (uint32_t)h2 | ((uint32_t)h3 << 16);
    lu.x = (uint32_t)l0 | ((uint32_t)l1 << 16);
    lu.y = (uint32_t)l2 | ((uint32_t)l3 << 16);
    *(uint2*)(hi + (size_t)i * 4) = hu;
    *(uint2*)(lo + (size_t)i * 4) = lu;
}

// ---------------- xdbl GEMM: [2][ML][96], B/C interleaved in cols 64..95 --------
__global__ __launch_bounds__(128)
void xdbl_gemm(const float* __restrict__ xcA,
               const float* __restrict__ xw0,
               const float* __restrict__ xw1,
               float* __restrict__ out)
{
    __shared__ float As[16][36];
    __shared__ float Bs[16][100];
    const int dir = blockIdx.z;
    const float* A = xcA + (size_t)dir * ML * DIN + (size_t)blockIdx.x * 32 * DIN;
    const float* B = dir ? xw1 : xw0;
    float* C = out + (size_t)dir * ML * 96 + (size_t)blockIdx.x * 32 * 96;

    const int tid = threadIdx.x;
    const int tx = tid & 15, ty = tid >> 4;
    float acc[4][6];
    #pragma unroll
    for (int i = 0; i < 4; i++)
        #pragma unroll
        for (int j = 0; j < 6; j++) acc[i][j] = 0.f;

    const int ar = tid >> 2, akc = (tid & 3) * 4;

    for (int k0 = 0; k0 < DIN; k0 += 16) {
        {
            float4 v = *(const float4*)(A + (size_t)ar * DIN + k0 + akc);
            As[akc+0][ar] = v.x; As[akc+1][ar] = v.y;
            As[akc+2][ar] = v.z; As[akc+3][ar] = v.w;
        }
        #pragma unroll
        for (int j = 0; j < 3; j++) {
            int i = tid + j * 128;
            int n = i >> 2, kc = (i & 3) * 4;
            float4 v = *(const float4*)(B + (size_t)n * DIN + k0 + kc);
            Bs[kc+0][n] = v.x; Bs[kc+1][n] = v.y;
            Bs[kc+2][n] = v.z; Bs[kc+3][n] = v.w;
        }
        __syncthreads();
        #pragma unroll
        for (int kk = 0; kk < 16; kk++) {
            float4 a4 = *(const float4*)&As[kk][ty*4];
            float ar4[4] = {a4.x, a4.y, a4.z, a4.w};
            float2 b0 = *(const float2*)&Bs[kk][tx*6];
            float2 b1 = *(const float2*)&Bs[kk][tx*6+2];
            float2 b2 = *(const float2*)&Bs[kk][tx*6+4];
            float br[6] = {b0.x, b0.y, b1.x, b1.y, b2.x, b2.y};
            #pragma unroll
            for (int i = 0; i < 4; i++)
                #pragma unroll
                for (int j = 0; j < 6; j++)
                    acc[i][j] = fmaf(ar4[i], br[j], acc[i][j]);
        }
        __syncthreads();
    }
    #pragma unroll
    for (int i = 0; i < 4; i++)
        #pragma unroll
        for (int j = 0; j < 6; j++) {
            int c = tx*6 + j;
            int cw = (c < 64) ? c : ((c < 80) ? (64 + 2*(c - 64)) : (65 + 2*(c - 80)));
            C[(size_t)(ty*4+i) * 96 + cw] = acc[i][j];
        }
}

// ---------------- dt GEMM -> (dt, u) float2 pairs (R6 form) ----------------------
__global__ __launch_bounds__(256)
void dt_gemm(const float* __restrict__ xdblA,
             const float* __restrict__ xcA,
             const float* __restrict__ w0, const float* __restrict__ w1,
             const float* __restrict__ b0, const float* __restrict__ b1,
             float* __restrict__ out)          // [2][ML][DIN][2]
{
    __shared__ float As[16][132];
    __shared__ float Bs[16][132];

    const int dir = blockIdx.z;
    const float* A = xdblA + (size_t)dir * ML * 96;
    const float* xcD = xcA + (size_t)dir * ML * DIN;
    const float* Bw = dir ? w1 : w0;
    const float* bias = dir ? b1 : b0;
    float* C = out + (size_t)dir * ML * DIN * 2;

    const int tid = threadIdx.x;
    const int tx = tid & 15;
    const int ty = tid >> 4;
    const int rowBase = blockIdx.y * 128;
    const int colBase = blockIdx.x * 128;

    const int lm = tid >> 1;
    const int lk = (tid & 1) * 8;

    const float* aPtr = A + (size_t)(rowBase + lm) * 96 + lk;
    const float* bPtr = Bw + (size_t)(colBase + lm) * RDT + lk;

    float acc[8][8];
    #pragma unroll
    for (int i = 0; i < 8; i++)
        #pragma unroll
        for (int j = 0; j < 8; j++) acc[i][j] = 0.f;

    for (int k0 = 0; k0 < RDT; k0 += 16) {
        float4 a0 = *(const float4*)(aPtr + k0);
        float4 a1 = *(const float4*)(aPtr + k0 + 4);
        float4 b0v = *(const float4*)(bPtr + k0);
        float4 b1v = *(const float4*)(bPtr + k0 + 4);

        As[lk+0][lm] = a0.x; As[lk+1][lm] = a0.y; As[lk+2][lm] = a0.z; As[lk+3][lm] = a0.w;
        As[lk+4][lm] = a1.x; As[lk+5][lm] = a1.y; As[lk+6][lm] = a1.z; As[lk+7][lm] = a1.w;
        Bs[lk+0][lm] = b0v.x; Bs[lk+1][lm] = b0v.y; Bs[lk+2][lm] = b0v.z; Bs[lk+3][lm] = b0v.w;
        Bs[lk+4][lm] = b1v.x; Bs[lk+5][lm] = b1v.y; Bs[lk+6][lm] = b1v.z; Bs[lk+7][lm] = b1v.w;
        __syncthreads();

        #pragma unroll
        for (int kk = 0; kk < 16; kk++) {
            float4 ra0 = *(const float4*)&As[kk][ty * 4];
            float4 ra1 = *(const float4*)&As[kk][64 + ty * 4];
            float4 rb0 = *(const float4*)&Bs[kk][tx * 4];
            float4 rb1 = *(const float4*)&Bs[kk][64 + tx * 4];
            float ar[8] = {ra0.x, ra0.y, ra0.z, ra0.w, ra1.x, ra1.y, ra1.z, ra1.w};
            float br[8] = {rb0.x, rb0.y, rb0.z, rb0.w, rb1.x, rb1.y, rb1.z, rb1.w};
            #pragma unroll
            for (int i = 0; i < 8; i++)
                #pragma unroll
                for (int j = 0; j < 8; j++)
                    acc[i][j] = fmaf(ar[i], br[j], acc[i][j]);
        }
        __syncthreads();
    }

    #pragma unroll
    for (int i = 0; i < 8; i++) {
        int r = rowBase + ((i < 4) ? (ty * 4 + i) : (64 + ty * 4 + i - 4));
        #pragma unroll
        for (int j = 0; j < 8; j++) {
            int c = colBase + ((j < 4) ? (tx * 4 + j) : (64 + tx * 4 + j - 4));
            float dtv = softplusf(acc[i][j] + bias[c]);
            float uv  = xcD[(size_t)r * DIN + c];
            *(float2*)&C[((size_t)r * DIN + c) * 2] = make_float2(dtv, uv);
        }
    }
}

// ---------------- depthwise causal conv (k=4, dir-dependent taps) ---------------
__global__ void conv_kernel(const float* __restrict__ xz,
                            const float* __restrict__ cw0, const float* __restrict__ cw1,
                            const float* __restrict__ cb0, const float* __restrict__ cb1,
                            float* __restrict__ xc)
{
    int idx = blockIdx.x * blockDim.x + threadIdx.x;
    if (idx >= 2 * ML * DIN) return;
    int dir = idx >= ML * DIN;
    int li = dir ? (idx - ML * DIN) : idx;
    int c = li & (DIN - 1);
    int r = li / DIN;
    int l = r & (LS - 1);
    int b = r >> 11;
    const float* cw = dir ? cw1 : cw0;
    const float* cb = dir ? cb1 : cb0;
    float acc = cb[c];
    float w0 = cw[c*4+0], w1 = cw[c*4+1], w2 = cw[c*4+2], w3 = cw[c*4+3];
    size_t colOff = (size_t)dir * 4096 + c;
    if (!dir) {
        #pragma unroll
        for (int k = 0; k < 4; k++) {
            int lp = l - 3 + k;
            if (lp >= 0) {
                float w = (k==0)?w0:(k==1)?w1:(k==2)?w2:w3;
                acc += xz[(size_t)(b * LS + lp) * 8192 + colOff] * w;
            }
        }
    } else {
        #pragma unroll
        for (int k = 0; k < 4; k++) {
            int lp = l + 3 - k;
            if (lp < LS) {
                float w = (k==0)?w0:(k==1)?w1:(k==2)?w2:w3;
                acc += xz[(size_t)(b * LS + lp) * 8192 + colOff] * w;
            }
        }
    }
    xc[(size_t)dir * ML * DIN + (size_t)r * DIN + c] = siluf(acc);
}

// ---------------- selective scan: (dir,b,16d) blocks, row-major inputs,
//                  smem-staged coalesced y stores -------------------------------
__global__ __launch_bounds__(256)
void scan_kernel(const float* __restrict__ dtu,   // [2][ML][DIN][2]
                 const float* __restrict__ xdbl,  // [2][ML][96] (B/C paired)
                 const float* __restrict__ xz,    // [ML][8192]
                 const float* __restrict__ A0, const float* __restrict__ A1,
                 const float* __restrict__ D0, const float* __restrict__ D1,
                 bf16* __restrict__ yhi, bf16* __restrict__ ylo)
{
    __shared__ unsigned short syh[32][16];
    __shared__ unsigned short syl[32][16];

    const int tid  = threadIdx.x;
    const int wid  = tid >> 5;
    const int lane = tid & 31;
    const int half = lane >> 4;
    const int s    = lane & 15;

    const int dg  = blockIdx.x & 127;
    const int b   = (blockIdx.x >> 7) & 1;
    const int dir = blockIdx.x >> 8;
    const int dloc = wid * 2 + half;       // 0..15
    const int d    = dg * 16 + dloc;

    const float* Alog = dir ? A1 : A0;
    const float Av = -__expf(Alog[d * DST + s]);
    const float Dd = (dir ? D1 : D0)[d];
    float h = 0.f;
    const bool w0lane = (s == 0);

    const size_t base = (size_t)b * LS;
    const int l0 = dir ? (LS - 1) : 0;
    const int step = dir ? -1 : 1;

    const float* pDtu = dtu + ((size_t)dir * ML * DIN + (base + l0) * DIN + d) * 2;
    const float* pBC  = xdbl + (size_t)dir * ML * 96 + (base + l0) * 96 + RDT + 2 * s;
    const float* pZ   = xz + (base + l0) * 8192 + (size_t)dir * 4096 + 2048 + d;
    const ptrdiff_t sDtu = (ptrdiff_t)step * DIN * 2;
    const ptrdiff_t sBC  = (ptrdiff_t)step * 96;
    const ptrdiff_t sZ   = (ptrdiff_t)step * 8192;
    const size_t yBase = (size_t)dir * ML * DIN + base * DIN;

    float2 du = *(const float2*)pDtu;
    float2 bc = *(const float2*)pBC;
    float zv  = w0lane ? *pZ : 0.f;

    for (int it = 0; it < LS; it++) {
        const bool more = (it + 1 < LS);
        float2 dun = more ? *(const float2*)(pDtu + sDtu) : du;
        float2 bcn = more ? *(const float2*)(pBC + sBC)   : bc;
        float zn   = (w0lane && more) ? *(pZ + sZ) : zv;

        h = h * __expf(du.x * Av) + du.x * du.y * bc.x;
        float y = h * bc.y;
        y += __shfl_xor_sync(0xffffffffu, y, 8);
        y += __shfl_xor_sync(0xffffffffu, y, 4);
        y += __shfl_xor_sync(0xffffffffu, y, 2);
        y += __shfl_xor_sync(0xffffffffu, y, 1);
        if (w0lane) {
            float yv = (y + du.y * Dd) * siluf(zv);
            __nv_bfloat16 hb = __float2bfloat16(yv);
            syh[it & 31][dloc] = __bfloat16_as_ushort(hb);
            syl[it & 31][dloc] =
                __bfloat16_as_ushort(__float2bfloat16(yv - __bfloat162float(hb)));
        }
        if ((it & 31) == 31) {
            __syncthreads();
            const int row = tid >> 3;        // 0..31
            const int cp  = tid & 7;         // 0..7
            const int itr = (it - 31) + row;
            const int gl  = l0 + step * itr;
            const size_t go = yBase + (size_t)gl * DIN + dg * 16 + 2 * cp;
            *(uint32_t*)(yhi + go) = *(const uint32_t*)&syh[row][2 * cp];
            *(uint32_t*)(ylo + go) = *(const uint32_t*)&syl[row][2 * cp];
            __syncthreads();
        }
        pDtu += sDtu; pBC += sBC; pZ += sZ;
        du = dun; bc = bcn; zv = zn;
    }
}

// ---------------- fused residual + layernorm -> xsum + bf16 hi/lo ----------------
__global__ void resln_kernel(const float* __restrict__ x,
                             const float* __restrict__ y0,
                             const float* __restrict__ y1,
                             const float* __restrict__ g,
                             const float* __restrict__ bta,
                             float* __restrict__ xsum,
                             bf16* __restrict__ outhi,
                             bf16* __restrict__ outlo)
{
    int row = blockIdx.x;
    size_t off4 = (size_t)row * (DM / 4) + threadIdx.x;
    float4 xv = ((const float4*)x)[off4];
    float4 a = ((const float4*)y0)[off4];
    float4 b = ((const float4*)y1)[off4];
    float4 v;
    v.x = xv.x + 0.5f * (a.x + b.x);
    v.y = xv.y + 0.5f * (a.y + b.y);
    v.z = xv.z + 0.5f * (a.z + b.z);
    v.w = xv.w + 0.5f * (a.w + b.w);
    ((float4*)xsum)[off4] = v;

    float s  = v.x + v.y + v.z + v.w;
    float sq = v.x*v.x + v.y*v.y + v.z*v.z + v.w*v.w;
    #pragma unroll
    for (int o = 16; o >= 1; o >>= 1) {
        s  += __shfl_xor_sync(0xffffffffu, s, o);
        sq += __shfl_xor_sync(0xffffffffu, sq, o);
    }
    __shared__ float ss[8], ssq[8];
    int warp = threadIdx.x >> 5, lane = threadIdx.x & 31;
    if (lane == 0) { ss[warp] = s; ssq[warp] = sq; }
    __syncthreads();
    __shared__ float sh_mean, sh_inv;
    if (threadIdx.x == 0) {
        float ts = 0.f, tq = 0.f;
        #pragma unroll
        for (int w = 0; w < 8; w++) { ts += ss[w]; tq += ssq[w]; }
        float mean = ts / DM;
        float var = tq / DM - mean * mean;
        sh_mean = mean;
        sh_inv = rsqrtf(var + 1e-5f);
    }
    __syncthreads();
    float mean = sh_mean, inv = sh_inv;
    float4 gv = ((const float4*)g)[threadIdx.x];
    float4 bv = ((const float4*)bta)[threadIdx.x];
    float o0 = (v.x - mean) * inv * gv.x + bv.x;
    float o1 = (v.y - mean) * inv * gv.y + bv.y;
    float o2 = (v.z - mean) * inv * gv.z + bv.z;
    float o3 = (v.w - mean) * inv * gv.w + bv.w;
    unsigned short h0,h1,h2,h3,l0,l1,l2,l3;
    split1(o0, h0, l0); split1(o1, h1, l1);
    split1(o2, h2, l2); split1(o3, h3, l3);
    uint2 hu, lu;
    hu.x = (uint32_t)h0 | ((uint32_t)h1 << 16);
    hu.y = (uint32_t)h2 | ((uint32_t)h3 << 16);
    lu.x = (uint32_t)l0 | ((uint32_t)l1 << 16);
    lu.y = (uint32_t)l2 | ((uint32_t)l3 << 16);
    size_t off = (size_t)row * DM + threadIdx.x * 4;
    *(uint2*)(outhi + off) = hu;
    *(uint2*)(outlo + off) = lu;
}

// ---------------- host orchestration ----------------------------------------------
extern "C" void kernel_launch(void* const* d_in, const int* in_sizes, int n_in,
                              void* d_out, int out_size)
{
    (void)in_sizes; (void)n_in; (void)out_size;

    const float* x = (const float*)d_in[0];
    const float* in_w[2]   = { (const float*)d_in[1],  (const float*)d_in[10] };
    const float* conv_w[2] = { (const float*)d_in[2],  (const float*)d_in[11] };
    const float* conv_b[2] = { (const float*)d_in[3],  (const float*)d_in[12] };
    const float* x_w[2]    = { (const float*)d_in[4],  (const float*)d_in[13] };
    const float* dt_w[2]   = { (const float*)d_in[5],  (const float*)d_in[14] };
    const float* dt_b[2]   = { (const float*)d_in[6],  (const float*)d_in[15] };
    const float* A_log[2]  = { (const float*)d_in[7],  (const float*)d_in[16] };
    const float* Dp[2]     = { (const float*)d_in[8],  (const float*)d_in[17] };
    const float* out_w[2]  = { (const float*)d_in[9],  (const float*)d_in[18] };
    const float* ff_ln_g = (const float*)d_in[19];
    const float* ff_ln_b = (const float*)d_in[20];
    const float* ff_w1   = (const float*)d_in[21];
    const float* ff_b1   = (const float*)d_in[22];
    const float* ff_w2   = (const float*)d_in[23];
    const float* ff_b2   = (const float*)d_in[24];

    float *xz, *xc, *xdbl, *dtu, *ydir, *xsum;
    bf16 *xhi, *xlo, *yhi, *ylo, *lnhi, *lnlo, *f1hi, *f1lo;
    bf16 *inwhi, *inwlo, *outwhi, *outwlo, *w1hi, *w1lo, *w2hi, *w2lo;
    cudaGetSymbolAddress((void**)&xz,   g_xz);
    cudaGetSymbolAddress((void**)&xc,   g_xc);
    cudaGetSymbolAddress((void**)&xdbl, g_xdbl);
    cudaGetSymbolAddress((void**)&dtu,  g_dtu);
    cudaGetSymbolAddress((void**)&ydir, g_ydir);
    cudaGetSymbolAddress((void**)&xsum, g_xsum);
    cudaGetSymbolAddress((void**)&xhi,  g_xhi);
    cudaGetSymbolAddress((void**)&xlo,  g_xlo);
    cudaGetSymbolAddress((void**)&yhi,  g_yhi);
    cudaGetSymbolAddress((void**)&ylo,  g_ylo);
    cudaGetSymbolAddress((void**)&lnhi, g_lnhi);
    cudaGetSymbolAddress((void**)&lnlo, g_lnlo);
    cudaGetSymbolAddress((void**)&f1hi, g_f1hi);
    cudaGetSymbolAddress((void**)&f1lo, g_f1lo);
    cudaGetSymbolAddress((void**)&inwhi,  g_inwhi);
    cudaGetSymbolAddress((void**)&inwlo,  g_inwlo);
    cudaGetSymbolAddress((void**)&outwhi, g_outwhi);
    cudaGetSymbolAddress((void**)&outwlo, g_outwlo);
    cudaGetSymbolAddress((void**)&w1hi, g_w1hi);
    cudaGetSymbolAddress((void**)&w1lo, g_w1lo);
    cudaGetSymbolAddress((void**)&w2hi, g_w2hi);
    cudaGetSymbolAddress((void**)&w2lo, g_w2lo);

    cudaFuncSetAttribute(mma_gemm2, cudaFuncAttributeMaxDynamicSharedMemorySize, DSMEM2);

    const size_t szXC   = (size_t)ML * DIN;
    const size_t szYDIR = (size_t)ML * DM;
    const size_t szINW  = (size_t)2 * DIN * DM;
    const size_t szOUTW = (size_t)DM * DIN;

    dim3 blk(256);

    // idx 0-2: splits needed for in-proj
    split_kernel<<<(ML*DM/4 + 255)/256, blk>>>(x, xhi, xlo, ML*DM/4);
    split_kernel<<<((int)szINW/4 + 255)/256, blk>>>(in_w[0], inwhi,         inwlo,         (int)szINW/4);
    split_kernel<<<((int)szINW/4 + 255)/256, blk>>>(in_w[1], inwhi + szINW, inwlo + szINW, (int)szINW/4);

    // idx 3 (profiled): merged in-proj, M=4096, N=8192, K=1024
    mma_gemm2<<<dim3(64, 32, 1), blk, DSMEM2>>>(
        xhi, xlo, DM, inwhi, inwlo, DM,
        nullptr, nullptr, xz, nullptr, nullptr,
        8192, DM, 0, 0, 0, 0);

    // remaining splits
    split_kernel<<<(DFF*DM/4 + 255)/256, blk>>>(ff_w1, w1hi, w1lo, DFF*DM/4);
    split_kernel<<<((int)szOUTW/4 + 255)/256, blk>>>(out_w[0], outwhi,          outwlo,          (int)szOUTW/4);
    split_kernel<<<((int)szOUTW/4 + 255)/256, blk>>>(out_w[1], outwhi + szOUTW, outwlo + szOUTW, (int)szOUTW/4);
    split_kernel<<<(DM*DFF/4 + 255)/256, blk>>>(ff_w2, w2hi, w2lo, DM*DFF/4);

    // conv (both dirs)
    conv_kernel<<<(2*ML*DIN + 255)/256, blk>>>(xz, conv_w[0], conv_w[1],
                                               conv_b[0], conv_b[1], xc);

    // xdbl (both dirs), B/C interleaved
    xdbl_gemm<<<dim3(ML/32, 1, 2), dim3(128)>>>(xc, x_w[0], x_w[1], xdbl);

    // dt (both dirs) -> (dt, u) pairs
    dt_gemm<<<dim3(DIN/128, ML/128, 2), blk>>>(xdbl, xc, dt_w[0], dt_w[1],
                                               dt_b[0], dt_b[1], dtu);

    // scan (both dirs): 512 blocks = 2 dir x 2 b x 128 d-groups
    scan_kernel<<<512, blk>>>(dtu, xdbl, xz, A_log[0], A_log[1],
                              Dp[0], Dp[1], yhi, ylo);

    // out-proj (both dirs via z)
    mma_gemm2<<<dim3(8, 32, 2), blk, DSMEM2>>>(
        yhi, ylo, DIN, outwhi, outwlo, DIN,
        nullptr, nullptr, ydir, nullptr, nullptr,
        DM, DIN, 0, szXC, szOUTW, szYDIR);

    // fused residual + LN
    resln_kernel<<<ML, blk>>>(x, ydir, ydir + szYDIR, ff_ln_g, ff_ln_b,
                              xsum, lnhi, lnlo);

    // ff1 = silu(ln @ ff_w1^T + b1) -> bf16 hi/lo
    mma_gemm2<<<dim3(32, 32, 1), blk, DSMEM2>>>(
        lnhi, lnlo, DM, w1hi, w1lo, DM,
        ff_b1, nullptr, nullptr, f1hi, f1lo,
        DFF, DM, 1, 0, 0, 0);

    // out = xsum + (ff1 @ ff_w2^T + b2)
    mma_gemm2<<<dim3(8, 32, 1), blk, DSMEM2>>>(
        f1hi, f1lo, DFF, w2hi, w2lo, DFF,
        ff_b2, xsum, (float*)d_out, nullptr, nullptr,
        DM, DFF, 0, 0, 0, 0);
}